// round 12
// baseline (speedup 1.0000x reference)
#include <cuda_runtime.h>
#include <math.h>

#define NN 100000
#define NE 1600000
#define NG 512
#define NF 64
#define H1 128
#define H2 64
#define SCB 98            // scan blocks: ceil(NN/1024)
#define S2SCAP 320        // max cached nodes per graph in s2s
#define DBLK 3125         // dense blocks: NN/32

// ---------------- device scratch ----------------
__device__ float g_h1[NN * H1];
__device__ float g_s1[NN * H1];
__device__ float g_h2[NN * H2];
__device__ float g_e[NN];
__device__ int   g_cnt[NN];
__device__ int   g_off[NN + 1];
__device__ int   g_cur[NN];
__device__ int   g_csr[NE];
__device__ int   g_gs[NG + 1];
__device__ int   g_sagg[SCB];
__device__ int   g_sflag[SCB];

__device__ __forceinline__ float gelu_f(float x) {
    return 0.5f * x * (1.0f + erff(x * 0.70710678118654752f));
}
__device__ __forceinline__ float sigmoid_f(float x) {
    return 1.0f / (1.0f + expf(-x));
}

// ---------------- init ----------------
__global__ void __launch_bounds__(256) k_zero() {
    int i = blockIdx.x * blockDim.x + threadIdx.x;
    int T = gridDim.x * blockDim.x;
    for (int j = i; j < NN; j += T) { g_cnt[j] = 0; g_cur[j] = 0; }
    if (i < SCB) { g_sflag[i] = 0; g_sagg[i] = 0; }
    if (i == 0) g_off[NN] = NE;
}

// ---------------- nfc: 32 rows/block, 4 rows/warp, float4 broadcasts + count fold ----------------
__global__ void __launch_bounds__(256) k_nfc(const float* __restrict__ x,
                                             const float* __restrict__ W,
                                             const float* __restrict__ b,
                                             const int* __restrict__ ei) {
    extern __shared__ float sm[];
    float* wt = sm;                  // [64][128] transposed (32 KB)
    float* xs = sm + NF * H1;        // [32][64]  (8 KB)
    int tid = threadIdx.x;
    // edge counting fold: 512 edges per block
    {
        int eb = blockIdx.x * 512 + tid * 2;
        if (eb < NE)     atomicAdd(&g_cnt[ei[NE + eb]], 1);
        if (eb + 1 < NE) atomicAdd(&g_cnt[ei[NE + eb + 1]], 1);
    }
    for (int i = tid; i < H1 * NF; i += 256) {
        int o = i >> 6, k = i & 63;
        wt[k * H1 + o] = W[i];
    }
    int warp = tid >> 5, lane = tid & 31;
    int nb = blockIdx.x * 32;
    // stage 32 rows of x
    for (int i = tid; i < 32 * NF / 2; i += 256) {
        int row = (i * 2) >> 6;
        int c   = (i * 2) & 63;
        *(float2*)&xs[row * NF + c] = *(const float2*)&x[(nb + row) * NF + c];
    }
    __syncthreads();
    float4 bias = *(const float4*)&b[lane * 4];
    float4 acc[4];
#pragma unroll
    for (int t = 0; t < 4; t++) acc[t] = bias;
    const float* r0 = &xs[(warp * 4 + 0) * NF];
    const float* r1 = &xs[(warp * 4 + 1) * NF];
    const float* r2 = &xs[(warp * 4 + 2) * NF];
    const float* r3 = &xs[(warp * 4 + 3) * NF];
    for (int k = 0; k < NF; k += 4) {
        float rv[4][4];
        *(float4*)rv[0] = *(const float4*)&r0[k];
        *(float4*)rv[1] = *(const float4*)&r1[k];
        *(float4*)rv[2] = *(const float4*)&r2[k];
        *(float4*)rv[3] = *(const float4*)&r3[k];
#pragma unroll
        for (int kk = 0; kk < 4; kk++) {
            float4 w = *(const float4*)&wt[(k + kk) * H1 + lane * 4];
#pragma unroll
            for (int t = 0; t < 4; t++) {
                float v = rv[t][kk];
                acc[t].x = fmaf(v, w.x, acc[t].x);
                acc[t].y = fmaf(v, w.y, acc[t].y);
                acc[t].z = fmaf(v, w.z, acc[t].z);
                acc[t].w = fmaf(v, w.w, acc[t].w);
            }
        }
    }
#pragma unroll
    for (int t = 0; t < 4; t++) {
        int n = nb + warp * 4 + t;
        float4 a = acc[t];
        a.x = gelu_f(a.x); a.y = gelu_f(a.y);
        a.z = gelu_f(a.z); a.w = gelu_f(a.w);
        *(float4*)&g_h1[n * H1 + lane * 4] = a;
    }
}

// ---------------- single-pass scan (decoupled lookback) + gstart fold ----------------
__global__ void __launch_bounds__(256) k_scan(const int* __restrict__ batch) {
    __shared__ int sm[256];
    __shared__ int addsh;
    int tid = threadIdx.x;
    int b = blockIdx.x;
    if (tid == 0) addsh = 0;
    int idx = b * 1024 + tid * 4;
    int v0 = 0, v1 = 0, v2 = 0, v3 = 0;
    if (idx     < NN) v0 = g_cnt[idx];
    if (idx + 1 < NN) v1 = g_cnt[idx + 1];
    if (idx + 2 < NN) v2 = g_cnt[idx + 2];
    if (idx + 3 < NN) v3 = g_cnt[idx + 3];
    int t = v0 + v1 + v2 + v3;
    sm[tid] = t;
    __syncthreads();
    for (int off = 1; off < 256; off <<= 1) {
        int u = (tid >= off) ? sm[tid - off] : 0;
        __syncthreads();
        sm[tid] += u;
        __syncthreads();
    }
    if (tid == 0) {
        g_sagg[b] = sm[255];
        __threadfence();
        atomicExch(&g_sflag[b], 1);
    }
    int excl = sm[tid] - t;
    int myadd = 0;
    for (int i = tid; i < b; i += 256) {
        while (((volatile int*)g_sflag)[i] == 0) { }
        myadd += ((volatile int*)g_sagg)[i];
    }
#pragma unroll
    for (int off = 16; off; off >>= 1) myadd += __shfl_xor_sync(0xFFFFFFFFu, myadd, off);
    if ((tid & 31) == 0 && myadd) atomicAdd(&addsh, myadd);
    __syncthreads();
    int add = addsh;
    if (idx     < NN) g_off[idx]     = excl + add;
    if (idx + 1 < NN) g_off[idx + 1] = excl + add + v0;
    if (idx + 2 < NN) g_off[idx + 2] = excl + add + v0 + v1;
    if (idx + 3 < NN) g_off[idx + 3] = excl + add + v0 + v1 + v2;
#pragma unroll
    for (int i = 0; i < 4; i++) {
        int n = idx + i;
        if (n < NN) {
            int bb = batch[n];
            int bp = (n == 0) ? -1 : batch[n - 1];
            for (int g = bp + 1; g <= bb; g++) g_gs[g] = n;
            if (n == NN - 1)
                for (int g = bb + 1; g <= NG; g++) g_gs[g] = NN;
        }
    }
}

__global__ void __launch_bounds__(256) k_scatter(const int* __restrict__ ei) {
    int e = blockIdx.x * blockDim.x + threadIdx.x;
    if (e < NE) {
        int s = ei[e];
        int d = ei[NE + e];
        int pos = atomicAdd(&g_cur[d], 1);
        g_csr[g_off[d] + pos] = s;
    }
}

// ---------------- gemm1t: g_s1 = g_h1 @ W1.T (no bias/act), k-split staging ----------------
__global__ void __launch_bounds__(256) k_gemm1t(const float* __restrict__ W) {
    extern __shared__ float sm[];
    float* wt = sm;                  // [64][128] transposed half (32 KB)
    float* as = sm + 64 * H1;        // [32][128] (16 KB)
    int tid = threadIdx.x;
    int nb = blockIdx.x * 32;
    for (int i = tid; i < 32 * H1 / 4; i += 256) {
        int row = (i * 4) >> 7;
        int k   = (i * 4) & 127;
        *(float4*)&as[row * H1 + k] = *(const float4*)&g_h1[(nb + row) * H1 + k];
    }
    int warp = tid >> 5, lane = tid & 31;
    float4 acc[4];
#pragma unroll
    for (int t = 0; t < 4; t++) acc[t] = make_float4(0.f, 0.f, 0.f, 0.f);
#pragma unroll
    for (int h = 0; h < 2; h++) {
        int k0 = h * 64;
        if (h) __syncthreads();   // all warps done with previous wt half
        for (int i = tid; i < H1 * 64; i += 256) {
            int o = i >> 6, kl = i & 63;
            wt[kl * H1 + o] = W[o * H1 + k0 + kl];
        }
        __syncthreads();
        const float* r0 = &as[(warp * 4 + 0) * H1 + k0];
        const float* r1 = &as[(warp * 4 + 1) * H1 + k0];
        const float* r2 = &as[(warp * 4 + 2) * H1 + k0];
        const float* r3 = &as[(warp * 4 + 3) * H1 + k0];
        for (int k = 0; k < 64; k += 4) {
            float rv[4][4];
            *(float4*)rv[0] = *(const float4*)&r0[k];
            *(float4*)rv[1] = *(const float4*)&r1[k];
            *(float4*)rv[2] = *(const float4*)&r2[k];
            *(float4*)rv[3] = *(const float4*)&r3[k];
#pragma unroll
            for (int kk = 0; kk < 4; kk++) {
                float4 w = *(const float4*)&wt[(k + kk) * H1 + lane * 4];
#pragma unroll
                for (int t = 0; t < 4; t++) {
                    float v = rv[t][kk];
                    acc[t].x = fmaf(v, w.x, acc[t].x);
                    acc[t].y = fmaf(v, w.y, acc[t].y);
                    acc[t].z = fmaf(v, w.z, acc[t].z);
                    acc[t].w = fmaf(v, w.w, acc[t].w);
                }
            }
        }
    }
#pragma unroll
    for (int t = 0; t < 4; t++) {
        int n = nb + warp * 4 + t;
        *(float4*)&g_s1[n * H1 + lane * 4] = acc[t];
    }
}

// ---------------- gatherB: agg z1 (g_s1) -> +b1, gelu -> g_h1 ----------------
__global__ void __launch_bounds__(256) k_gatherB(const float* __restrict__ b1) {
    int n = (blockIdx.x * 256 + threadIdx.x) >> 5;
    int lane = threadIdx.x & 31;
    if (n >= NN) return;
    const float* src = g_s1;
    float4 a = *(const float4*)&src[n * H1 + lane * 4];
    int e0 = g_off[n], e1 = g_off[n + 1];
    int j = e0;
    for (; j + 7 < e1; j += 8) {
        int s0 = g_csr[j],     s1 = g_csr[j + 1], s2 = g_csr[j + 2], s3 = g_csr[j + 3];
        int s4 = g_csr[j + 4], s5 = g_csr[j + 5], s6 = g_csr[j + 6], s7 = g_csr[j + 7];
        float4 v0 = *(const float4*)&src[s0 * H1 + lane * 4];
        float4 v1 = *(const float4*)&src[s1 * H1 + lane * 4];
        float4 v2 = *(const float4*)&src[s2 * H1 + lane * 4];
        float4 v3 = *(const float4*)&src[s3 * H1 + lane * 4];
        float4 v4 = *(const float4*)&src[s4 * H1 + lane * 4];
        float4 v5 = *(const float4*)&src[s5 * H1 + lane * 4];
        float4 v6 = *(const float4*)&src[s6 * H1 + lane * 4];
        float4 v7 = *(const float4*)&src[s7 * H1 + lane * 4];
        a.x += ((v0.x + v1.x) + (v2.x + v3.x)) + ((v4.x + v5.x) + (v6.x + v7.x));
        a.y += ((v0.y + v1.y) + (v2.y + v3.y)) + ((v4.y + v5.y) + (v6.y + v7.y));
        a.z += ((v0.z + v1.z) + (v2.z + v3.z)) + ((v4.z + v5.z) + (v6.z + v7.z));
        a.w += ((v0.w + v1.w) + (v2.w + v3.w)) + ((v4.w + v5.w) + (v6.w + v7.w));
    }
    if (j + 3 < e1) {
        int s0 = g_csr[j], s1 = g_csr[j + 1], s2 = g_csr[j + 2], s3 = g_csr[j + 3];
        float4 v0 = *(const float4*)&src[s0 * H1 + lane * 4];
        float4 v1 = *(const float4*)&src[s1 * H1 + lane * 4];
        float4 v2 = *(const float4*)&src[s2 * H1 + lane * 4];
        float4 v3 = *(const float4*)&src[s3 * H1 + lane * 4];
        a.x += (v0.x + v1.x) + (v2.x + v3.x);
        a.y += (v0.y + v1.y) + (v2.y + v3.y);
        a.z += (v0.z + v1.z) + (v2.z + v3.z);
        a.w += (v0.w + v1.w) + (v2.w + v3.w);
        j += 4;
    }
    for (; j < e1; j++) {
        int s0 = g_csr[j];
        float4 v0 = *(const float4*)&src[s0 * H1 + lane * 4];
        a.x += v0.x; a.y += v0.y; a.z += v0.z; a.w += v0.w;
    }
    float4 bb = *(const float4*)&b1[lane * 4];
    a.x = gelu_f(a.x + bb.x); a.y = gelu_f(a.y + bb.y);
    a.z = gelu_f(a.z + bb.z); a.w = gelu_f(a.w + bb.w);
    *(float4*)&g_h1[n * H1 + lane * 4] = a;
}

// ---------------- gather: g_h1 -> g_s1 (plain agg) ----------------
__global__ void __launch_bounds__(256) k_gather() {
    int n = (blockIdx.x * 256 + threadIdx.x) >> 5;
    int lane = threadIdx.x & 31;
    if (n >= NN) return;
    const float* src = g_h1;
    float4 a = *(const float4*)&src[n * H1 + lane * 4];
    int e0 = g_off[n], e1 = g_off[n + 1];
    int j = e0;
    for (; j + 7 < e1; j += 8) {
        int s0 = g_csr[j],     s1 = g_csr[j + 1], s2 = g_csr[j + 2], s3 = g_csr[j + 3];
        int s4 = g_csr[j + 4], s5 = g_csr[j + 5], s6 = g_csr[j + 6], s7 = g_csr[j + 7];
        float4 v0 = *(const float4*)&src[s0 * H1 + lane * 4];
        float4 v1 = *(const float4*)&src[s1 * H1 + lane * 4];
        float4 v2 = *(const float4*)&src[s2 * H1 + lane * 4];
        float4 v3 = *(const float4*)&src[s3 * H1 + lane * 4];
        float4 v4 = *(const float4*)&src[s4 * H1 + lane * 4];
        float4 v5 = *(const float4*)&src[s5 * H1 + lane * 4];
        float4 v6 = *(const float4*)&src[s6 * H1 + lane * 4];
        float4 v7 = *(const float4*)&src[s7 * H1 + lane * 4];
        a.x += ((v0.x + v1.x) + (v2.x + v3.x)) + ((v4.x + v5.x) + (v6.x + v7.x));
        a.y += ((v0.y + v1.y) + (v2.y + v3.y)) + ((v4.y + v5.y) + (v6.y + v7.y));
        a.z += ((v0.z + v1.z) + (v2.z + v3.z)) + ((v4.z + v5.z) + (v6.z + v7.z));
        a.w += ((v0.w + v1.w) + (v2.w + v3.w)) + ((v4.w + v5.w) + (v6.w + v7.w));
    }
    if (j + 3 < e1) {
        int s0 = g_csr[j], s1 = g_csr[j + 1], s2 = g_csr[j + 2], s3 = g_csr[j + 3];
        float4 v0 = *(const float4*)&src[s0 * H1 + lane * 4];
        float4 v1 = *(const float4*)&src[s1 * H1 + lane * 4];
        float4 v2 = *(const float4*)&src[s2 * H1 + lane * 4];
        float4 v3 = *(const float4*)&src[s3 * H1 + lane * 4];
        a.x += (v0.x + v1.x) + (v2.x + v3.x);
        a.y += (v0.y + v1.y) + (v2.y + v3.y);
        a.z += (v0.z + v1.z) + (v2.z + v3.z);
        a.w += (v0.w + v1.w) + (v2.w + v3.w);
        j += 4;
    }
    for (; j < e1; j++) {
        int s0 = g_csr[j];
        float4 v0 = *(const float4*)&src[s0 * H1 + lane * 4];
        a.x += v0.x; a.y += v0.y; a.z += v0.z; a.w += v0.w;
    }
    *(float4*)&g_s1[n * H1 + lane * 4] = a;
}

// ---------------- gemm2: g_h2 = normalize(gelu(g_s1 @ W.T + b)), k-split ----------------
__global__ void __launch_bounds__(256) k_gemm2(const float* __restrict__ W,
                                               const float* __restrict__ b,
                                               float* __restrict__ out_h) {
    extern __shared__ float sm[];
    float* wt = sm;                  // [64][64] transposed half (16 KB)
    float* as = sm + 64 * H2;        // [32][128] (16 KB)
    int tid = threadIdx.x;
    int nb = blockIdx.x * 32;
    for (int i = tid; i < 32 * H1 / 4; i += 256) {
        int row = (i * 4) >> 7;
        int k   = (i * 4) & 127;
        *(float4*)&as[row * H1 + k] = *(const float4*)&g_s1[(nb + row) * H1 + k];
    }
    int warp = tid >> 5, lane = tid & 31;
    float2 acc[4];
#pragma unroll
    for (int t = 0; t < 4; t++) acc[t] = make_float2(0.f, 0.f);
#pragma unroll
    for (int h = 0; h < 2; h++) {
        int k0 = h * 64;
        if (h) __syncthreads();
        for (int i = tid; i < H2 * 64; i += 256) {
            int o = i >> 6, kl = i & 63;
            wt[kl * H2 + o] = W[o * H1 + k0 + kl];
        }
        __syncthreads();
        const float* r0 = &as[(warp * 4 + 0) * H1 + k0];
        const float* r1 = &as[(warp * 4 + 1) * H1 + k0];
        const float* r2 = &as[(warp * 4 + 2) * H1 + k0];
        const float* r3 = &as[(warp * 4 + 3) * H1 + k0];
        for (int k = 0; k < 64; k += 4) {
            float rv[4][4];
            *(float4*)rv[0] = *(const float4*)&r0[k];
            *(float4*)rv[1] = *(const float4*)&r1[k];
            *(float4*)rv[2] = *(const float4*)&r2[k];
            *(float4*)rv[3] = *(const float4*)&r3[k];
#pragma unroll
            for (int kk = 0; kk < 4; kk++) {
                float2 w = *(const float2*)&wt[(k + kk) * H2 + lane * 2];
#pragma unroll
                for (int t = 0; t < 4; t++) {
                    float v = rv[t][kk];
                    acc[t].x = fmaf(v, w.x, acc[t].x);
                    acc[t].y = fmaf(v, w.y, acc[t].y);
                }
            }
        }
    }
    float2 bias = *(const float2*)&b[lane * 2];
#pragma unroll
    for (int t = 0; t < 4; t++) {
        int n = nb + warp * 4 + t;
        float2 a = acc[t];
        a.x = gelu_f(a.x + bias.x);
        a.y = gelu_f(a.y + bias.y);
        float ssq = a.x * a.x + a.y * a.y;
#pragma unroll
        for (int off = 16; off; off >>= 1) ssq += __shfl_xor_sync(0xFFFFFFFFu, ssq, off);
        float inv = 1.0f / fmaxf(sqrtf(ssq), 1e-12f);
        a.x *= inv; a.y *= inv;
        *(float2*)&g_h2[n * H2 + lane * 2] = a;
        if (out_h) *(float2*)&out_h[n * H2 + lane * 2] = a;
    }
}

// ---------------- fused Set2Set + final MLP, graph h2 cached in smem ----------------
__global__ void __launch_bounds__(256) k_s2s(
        const float* __restrict__ Wih0, const float* __restrict__ Whh0,
        const float* __restrict__ bih0, const float* __restrict__ bhh0,
        const float* __restrict__ Wih1, const float* __restrict__ Whh1,
        const float* __restrict__ bih1, const float* __restrict__ bhh1,
        const float* __restrict__ fc1W, const float* __restrict__ fc1b,
        const float* __restrict__ fc2W, const float* __restrict__ fc2b,
        float* __restrict__ z) {
    extern __shared__ float dyn[];
    float* cache = dyn;                 // [S2SCAP][H2]
    float* esm   = dyn + S2SCAP * H2;   // [S2SCAP]
    __shared__ float h0[H2], c0[H2], h1[H2], c1[H2], qs[2 * H2];
    __shared__ float gb[4 * H2], red[8], rbuf[8 * H2];
    __shared__ float smax, ssum;
    int g = blockIdx.x;
    int tid = threadIdx.x, warp = tid >> 5, lane = tid & 31;
    int gs = g_gs[g], ge = g_gs[g + 1];
    int nv = ge - gs;
    const float* hp;
    float* ep;
    if (nv <= S2SCAP) {
        const float4* s4 = (const float4*)&g_h2[gs * H2];
        float4* d4 = (float4*)cache;
        int tot = nv * (H2 / 4);
        for (int i = tid; i < tot; i += 256) d4[i] = s4[i];
        hp = cache; ep = esm;
    } else {
        hp = &g_h2[gs * H2]; ep = &g_e[gs];
    }
    if (tid < H2) { h0[tid] = 0.0f; c0[tid] = 0.0f; h1[tid] = 0.0f; c1[tid] = 0.0f; }
    if (tid < 2 * H2) qs[tid] = 0.0f;
    __syncthreads();

    for (int step = 0; step < 4; step++) {
        for (int r = warp; r < 4 * H2; r += 8) {
            const float* wi = &Wih0[r * 2 * H2];
            float p = wi[lane] * qs[lane] + wi[lane + 32] * qs[lane + 32]
                    + wi[lane + 64] * qs[lane + 64] + wi[lane + 96] * qs[lane + 96];
            const float* wh = &Whh0[r * H2];
            p += wh[lane] * h0[lane] + wh[lane + 32] * h0[lane + 32];
#pragma unroll
            for (int off = 16; off; off >>= 1) p += __shfl_xor_sync(0xFFFFFFFFu, p, off);
            if (lane == 0) gb[r] = p + bih0[r] + bhh0[r];
        }
        __syncthreads();
        if (tid < H2) {
            float i = sigmoid_f(gb[tid]);
            float f = sigmoid_f(gb[H2 + tid]);
            float gg = tanhf(gb[2 * H2 + tid]);
            float o = sigmoid_f(gb[3 * H2 + tid]);
            float c = f * c0[tid] + i * gg;
            c0[tid] = c;
            h0[tid] = o * tanhf(c);
        }
        __syncthreads();
        for (int r = warp; r < 4 * H2; r += 8) {
            const float* wi = &Wih1[r * H2];
            float p = wi[lane] * h0[lane] + wi[lane + 32] * h0[lane + 32];
            const float* wh = &Whh1[r * H2];
            p += wh[lane] * h1[lane] + wh[lane + 32] * h1[lane + 32];
#pragma unroll
            for (int off = 16; off; off >>= 1) p += __shfl_xor_sync(0xFFFFFFFFu, p, off);
            if (lane == 0) gb[r] = p + bih1[r] + bhh1[r];
        }
        __syncthreads();
        if (tid < H2) {
            float i = sigmoid_f(gb[tid]);
            float f = sigmoid_f(gb[H2 + tid]);
            float gg = tanhf(gb[2 * H2 + tid]);
            float o = sigmoid_f(gb[3 * H2 + tid]);
            float c = f * c1[tid] + i * gg;
            c1[tid] = c;
            float h = o * tanhf(c);
            h1[tid] = h;
            qs[tid] = h;
        }
        __syncthreads();
        float wmax = -3.4e38f;
        for (int li = warp; li < nv; li += 8) {
            float2 hv = *(const float2*)&hp[li * H2 + lane * 2];
            float e = hv.x * qs[lane * 2] + hv.y * qs[lane * 2 + 1];
#pragma unroll
            for (int off = 16; off; off >>= 1) e += __shfl_xor_sync(0xFFFFFFFFu, e, off);
            if (lane == 0) ep[li] = e;
            wmax = fmaxf(wmax, e);
        }
        if (lane == 0) red[warp] = wmax;
        __syncthreads();
        if (tid == 0) {
            float m = red[0];
            for (int w = 1; w < 8; w++) m = fmaxf(m, red[w]);
            smax = m;
        }
        __syncthreads();
        float m = smax;
        float ps = 0.0f;
        for (int li = tid; li < nv; li += 256) {
            float ex = expf(ep[li] - m);
            ep[li] = ex;
            ps += ex;
        }
#pragma unroll
        for (int off = 16; off; off >>= 1) ps += __shfl_xor_sync(0xFFFFFFFFu, ps, off);
        if (lane == 0) red[warp] = ps;
        __syncthreads();
        if (tid == 0) {
            float s = 0.0f;
            for (int w = 0; w < 8; w++) s += red[w];
            ssum = s;
        }
        __syncthreads();
        float inv = 1.0f / (ssum + 1e-16f);
        float rx = 0.0f, ry = 0.0f;
        for (int li = warp; li < nv; li += 8) {
            float a = ep[li] * inv;
            float2 hv = *(const float2*)&hp[li * H2 + lane * 2];
            rx = fmaf(a, hv.x, rx);
            ry = fmaf(a, hv.y, ry);
        }
        rbuf[warp * H2 + lane * 2]     = rx;
        rbuf[warp * H2 + lane * 2 + 1] = ry;
        __syncthreads();
        if (tid < H2) {
            float r = 0.0f;
            for (int w = 0; w < 8; w++) r += rbuf[w * H2 + tid];
            qs[H2 + tid] = r;
        }
        __syncthreads();
    }

    for (int r = warp; r < 32; r += 8) {
        const float* wr = &fc1W[r * 2 * H2];
        float p = wr[lane] * qs[lane] + wr[lane + 32] * qs[lane + 32]
                + wr[lane + 64] * qs[lane + 64] + wr[lane + 96] * qs[lane + 96];
#pragma unroll
        for (int off = 16; off; off >>= 1) p += __shfl_xor_sync(0xFFFFFFFFu, p, off);
        if (lane == 0) gb[r] = gelu_f(p + fc1b[r]);
    }
    __syncthreads();
    if (warp == 0) {
        float v = gb[lane] * fc2W[lane];
#pragma unroll
        for (int off = 16; off; off >>= 1) v += __shfl_xor_sync(0xFFFFFFFFu, v, off);
        if (lane == 0) z[g] = v + fc2b[0];
    }
}

// ---------------- host ----------------
extern "C" void kernel_launch(void* const* d_in, const int* in_sizes, int n_in,
                              void* d_out, int out_size) {
    const float* x     = (const float*)d_in[0];
    const int*   ei    = (const int*)d_in[1];
    const int*   batch = (const int*)d_in[2];
    const float* nfcW  = (const float*)d_in[3];
    const float* nfcb  = (const float*)d_in[4];
    const float* gc1W  = (const float*)d_in[5];
    const float* gc1b  = (const float*)d_in[6];
    const float* gc2W  = (const float*)d_in[7];
    const float* gc2b  = (const float*)d_in[8];
    const float* l0Wih = (const float*)d_in[9];
    const float* l0Whh = (const float*)d_in[10];
    const float* l0bih = (const float*)d_in[11];
    const float* l0bhh = (const float*)d_in[12];
    const float* l1Wih = (const float*)d_in[13];
    const float* l1Whh = (const float*)d_in[14];
    const float* l1bih = (const float*)d_in[15];
    const float* l1bhh = (const float*)d_in[16];
    const float* fc1W  = (const float*)d_in[17];
    const float* fc1b  = (const float*)d_in[18];
    const float* fc2W  = (const float*)d_in[19];
    const float* fc2b  = (const float*)d_in[20];

    float* out = (float*)d_out;
    float* out_h = (out_size >= NG + NN * H2) ? (out + NG) : nullptr;

    int gblk = (NN * 32 + 255) / 256;                     // 12500
    size_t sm_nfc   = (size_t)(NF * H1 + 32 * NF) * 4;    // 40 KB
    size_t sm_gemm1 = (size_t)(64 * H1 + 32 * H1) * 4;    // 48 KB
    size_t sm_gemm2 = (size_t)(64 * H2 + 32 * H1) * 4;    // 32 KB
    size_t sm_s2s   = (size_t)(S2SCAP * H2 + S2SCAP) * 4; // 83.2 KB
    cudaFuncSetAttribute(k_nfc,    cudaFuncAttributeMaxDynamicSharedMemorySize, (int)sm_nfc);
    cudaFuncSetAttribute(k_gemm1t, cudaFuncAttributeMaxDynamicSharedMemorySize, (int)sm_gemm1);
    cudaFuncSetAttribute(k_gemm2,  cudaFuncAttributeMaxDynamicSharedMemorySize, (int)sm_gemm2);
    cudaFuncSetAttribute(k_s2s,    cudaFuncAttributeMaxDynamicSharedMemorySize, (int)sm_s2s);

    k_zero<<<128, 256>>>();
    k_nfc<<<DBLK, 256, sm_nfc>>>(x, nfcW, nfcb, ei);
    k_scan<<<SCB, 256>>>(batch);
    k_scatter<<<(NE + 255) / 256, 256>>>(ei);
    k_gemm1t<<<DBLK, 256, sm_gemm1>>>(gc1W);
    k_gatherB<<<gblk, 256>>>(gc1b);
    k_gather<<<gblk, 256>>>();
    k_gemm2<<<DBLK, 256, sm_gemm2>>>(gc2W, gc2b, out_h);
    k_s2s<<<NG, 256, sm_s2s>>>(l0Wih, l0Whh, l0bih, l0bhh,
                               l1Wih, l1Whh, l1bih, l1bhh,
                               fc1W, fc1b, fc2W, fc2b, out);
}

// round 13
// speedup vs baseline: 1.1485x; 1.1485x over previous
#include <cuda_runtime.h>
#include <math.h>

#define NN 100000
#define NE 1600000
#define NG 512
#define NF 64
#define H1 128
#define H2 64
#define SCB 98            // scan blocks: ceil(NN/1024)
#define TPB 64            // nodes per block in dense kernels
#define S2SCAP 320        // max cached nodes per graph in s2s

// ---------------- device scratch ----------------
__device__ float g_h1[NN * H1];
__device__ float g_s1[NN * H1];
__device__ float g_h2[NN * H2];
__device__ float g_e[NN];
__device__ int   g_cnt[NN];
__device__ int   g_off[NN + 1];
__device__ int   g_cur[NN];
__device__ int   g_csr[NE];
__device__ int   g_gs[NG + 1];
__device__ int   g_sagg[SCB];
__device__ int   g_sflag[SCB];

__device__ __forceinline__ float gelu_f(float x) {
    return 0.5f * x * (1.0f + erff(x * 0.70710678118654752f));
}
__device__ __forceinline__ float sigmoid_f(float x) {
    return 1.0f / (1.0f + expf(-x));
}

// ---------------- init ----------------
__global__ void __launch_bounds__(256) k_zero() {
    int i = blockIdx.x * blockDim.x + threadIdx.x;
    int T = gridDim.x * blockDim.x;
    for (int j = i; j < NN; j += T) { g_cnt[j] = 0; g_cur[j] = 0; }
    if (i < SCB) { g_sflag[i] = 0; g_sagg[i] = 0; }
    if (i == 0) g_off[NN] = NE;
}

// ---------------- nfc (64 nodes/block) + edge counting fold ----------------
__global__ void __launch_bounds__(256) k_nfc(const float* __restrict__ x,
                                             const float* __restrict__ W,
                                             const float* __restrict__ b,
                                             const int* __restrict__ ei) {
    extern __shared__ float sm[];
    float* wt = sm;                  // [64][128] transposed (32 KB)
    float* xs = sm + NF * H1;        // [64][64]  (16 KB)
    int tid = threadIdx.x;
    {
        int eb = blockIdx.x * 1024 + tid * 4;
#pragma unroll
        for (int i = 0; i < 4; i++)
            if (eb + i < NE) atomicAdd(&g_cnt[ei[NE + eb + i]], 1);
    }
    for (int i = tid; i < H1 * NF; i += 256) {
        int o = i >> 6, k = i & 63;
        wt[k * H1 + o] = W[i];
    }
    int warp = tid >> 5, lane = tid & 31;
    int nb = blockIdx.x * TPB;
#pragma unroll
    for (int t = 0; t < 8; t++) {
        int row = warp * 8 + t;
        int n = nb + row;
        if (n < NN) {
            float2 xv = *(const float2*)&x[n * NF + lane * 2];
            *(float2*)&xs[row * NF + lane * 2] = xv;
        }
    }
    __syncthreads();
    float4 bias = *(const float4*)&b[lane * 4];
    float4 acc[8];
#pragma unroll
    for (int t = 0; t < 8; t++) acc[t] = bias;
    const float* rp = &xs[warp * 8 * NF];
    for (int k = 0; k < NF; k += 4) {
        float rv[8][4];
#pragma unroll
        for (int t = 0; t < 8; t++)
            *(float4*)rv[t] = *(const float4*)&rp[t * NF + k];
#pragma unroll
        for (int kk = 0; kk < 4; kk++) {
            float4 w = *(const float4*)&wt[(k + kk) * H1 + lane * 4];
#pragma unroll
            for (int t = 0; t < 8; t++) {
                float v = rv[t][kk];
                acc[t].x = fmaf(v, w.x, acc[t].x);
                acc[t].y = fmaf(v, w.y, acc[t].y);
                acc[t].z = fmaf(v, w.z, acc[t].z);
                acc[t].w = fmaf(v, w.w, acc[t].w);
            }
        }
    }
#pragma unroll
    for (int t = 0; t < 8; t++) {
        int n = nb + warp * 8 + t;
        if (n < NN) {
            float4 a = acc[t];
            a.x = gelu_f(a.x); a.y = gelu_f(a.y);
            a.z = gelu_f(a.z); a.w = gelu_f(a.w);
            *(float4*)&g_h1[n * H1 + lane * 4] = a;
        }
    }
}

// ---------------- single-pass scan (decoupled lookback) + gstart fold ----------------
__global__ void __launch_bounds__(256) k_scan(const int* __restrict__ batch) {
    __shared__ int sm[256];
    __shared__ int addsh;
    int tid = threadIdx.x;
    int b = blockIdx.x;
    if (tid == 0) addsh = 0;
    int idx = b * 1024 + tid * 4;
    int v0 = 0, v1 = 0, v2 = 0, v3 = 0;
    if (idx     < NN) v0 = g_cnt[idx];
    if (idx + 1 < NN) v1 = g_cnt[idx + 1];
    if (idx + 2 < NN) v2 = g_cnt[idx + 2];
    if (idx + 3 < NN) v3 = g_cnt[idx + 3];
    int t = v0 + v1 + v2 + v3;
    sm[tid] = t;
    __syncthreads();
    for (int off = 1; off < 256; off <<= 1) {
        int u = (tid >= off) ? sm[tid - off] : 0;
        __syncthreads();
        sm[tid] += u;
        __syncthreads();
    }
    if (tid == 0) {
        g_sagg[b] = sm[255];
        __threadfence();
        atomicExch(&g_sflag[b], 1);
    }
    int excl = sm[tid] - t;
    int myadd = 0;
    for (int i = tid; i < b; i += 256) {
        while (((volatile int*)g_sflag)[i] == 0) { }
        myadd += ((volatile int*)g_sagg)[i];
    }
#pragma unroll
    for (int off = 16; off; off >>= 1) myadd += __shfl_xor_sync(0xFFFFFFFFu, myadd, off);
    if ((tid & 31) == 0 && myadd) atomicAdd(&addsh, myadd);
    __syncthreads();
    int add = addsh;
    if (idx     < NN) g_off[idx]     = excl + add;
    if (idx + 1 < NN) g_off[idx + 1] = excl + add + v0;
    if (idx + 2 < NN) g_off[idx + 2] = excl + add + v0 + v1;
    if (idx + 3 < NN) g_off[idx + 3] = excl + add + v0 + v1 + v2;
#pragma unroll
    for (int i = 0; i < 4; i++) {
        int n = idx + i;
        if (n < NN) {
            int bb = batch[n];
            int bp = (n == 0) ? -1 : batch[n - 1];
            for (int g = bp + 1; g <= bb; g++) g_gs[g] = n;
            if (n == NN - 1)
                for (int g = bb + 1; g <= NG; g++) g_gs[g] = NN;
        }
    }
}

__global__ void __launch_bounds__(256) k_scatter(const int* __restrict__ ei) {
    int e = blockIdx.x * blockDim.x + threadIdx.x;
    if (e < NE) {
        int s = ei[e];
        int d = ei[NE + e];
        int pos = atomicAdd(&g_cur[d], 1);
        g_csr[g_off[d] + pos] = s;
    }
}

// ---------------- gather: warp per node, g_h1 -> g_s1 ----------------
__global__ void __launch_bounds__(256) k_gather() {
    int n = (blockIdx.x * 256 + threadIdx.x) >> 5;
    int lane = threadIdx.x & 31;
    if (n >= NN) return;
    const float* src = g_h1;
    float4 a = *(const float4*)&src[n * H1 + lane * 4];
    int e0 = g_off[n], e1 = g_off[n + 1];
    int j = e0;
    for (; j + 7 < e1; j += 8) {
        int s0 = g_csr[j],     s1 = g_csr[j + 1], s2 = g_csr[j + 2], s3 = g_csr[j + 3];
        int s4 = g_csr[j + 4], s5 = g_csr[j + 5], s6 = g_csr[j + 6], s7 = g_csr[j + 7];
        float4 v0 = *(const float4*)&src[s0 * H1 + lane * 4];
        float4 v1 = *(const float4*)&src[s1 * H1 + lane * 4];
        float4 v2 = *(const float4*)&src[s2 * H1 + lane * 4];
        float4 v3 = *(const float4*)&src[s3 * H1 + lane * 4];
        float4 v4 = *(const float4*)&src[s4 * H1 + lane * 4];
        float4 v5 = *(const float4*)&src[s5 * H1 + lane * 4];
        float4 v6 = *(const float4*)&src[s6 * H1 + lane * 4];
        float4 v7 = *(const float4*)&src[s7 * H1 + lane * 4];
        a.x += ((v0.x + v1.x) + (v2.x + v3.x)) + ((v4.x + v5.x) + (v6.x + v7.x));
        a.y += ((v0.y + v1.y) + (v2.y + v3.y)) + ((v4.y + v5.y) + (v6.y + v7.y));
        a.z += ((v0.z + v1.z) + (v2.z + v3.z)) + ((v4.z + v5.z) + (v6.z + v7.z));
        a.w += ((v0.w + v1.w) + (v2.w + v3.w)) + ((v4.w + v5.w) + (v6.w + v7.w));
    }
    if (j + 3 < e1) {
        int s0 = g_csr[j], s1 = g_csr[j + 1], s2 = g_csr[j + 2], s3 = g_csr[j + 3];
        float4 v0 = *(const float4*)&src[s0 * H1 + lane * 4];
        float4 v1 = *(const float4*)&src[s1 * H1 + lane * 4];
        float4 v2 = *(const float4*)&src[s2 * H1 + lane * 4];
        float4 v3 = *(const float4*)&src[s3 * H1 + lane * 4];
        a.x += (v0.x + v1.x) + (v2.x + v3.x);
        a.y += (v0.y + v1.y) + (v2.y + v3.y);
        a.z += (v0.z + v1.z) + (v2.z + v3.z);
        a.w += (v0.w + v1.w) + (v2.w + v3.w);
        j += 4;
    }
    for (; j < e1; j++) {
        int s0 = g_csr[j];
        float4 v0 = *(const float4*)&src[s0 * H1 + lane * 4];
        a.x += v0.x; a.y += v0.y; a.z += v0.z; a.w += v0.w;
    }
    *(float4*)&g_s1[n * H1 + lane * 4] = a;
}

// ---------------- gemm1: g_h1 = gelu(g_s1 @ W.T + b) ----------------
__global__ void __launch_bounds__(256) k_gemm1(const float* __restrict__ W,
                                               const float* __restrict__ b) {
    extern __shared__ float sm[];
    float* wt = sm;                  // [128][128] transposed (64 KB)
    float* as = sm + H1 * H1;        // [64][128] (32 KB)
    int tid = threadIdx.x;
    for (int i = tid; i < H1 * H1; i += 256) {
        int o = i >> 7, k = i & 127;
        wt[k * H1 + o] = W[i];
    }
    int nb = blockIdx.x * TPB;
    for (int i = tid; i < TPB * H1 / 4; i += 256) {
        int row = (i * 4) >> 7;
        int k   = (i * 4) & 127;
        int n = nb + row;
        float4 v = (n < NN) ? *(const float4*)&g_s1[n * H1 + k]
                            : make_float4(0.f, 0.f, 0.f, 0.f);
        *(float4*)&as[row * H1 + k] = v;
    }
    __syncthreads();
    int warp = tid >> 5, lane = tid & 31;
    float4 bias = *(const float4*)&b[lane * 4];
    float4 acc[8];
#pragma unroll
    for (int t = 0; t < 8; t++) acc[t] = bias;
    const float* rp = &as[warp * 8 * H1];
    for (int k = 0; k < H1; k += 4) {
        float rv[8][4];
#pragma unroll
        for (int t = 0; t < 8; t++)
            *(float4*)rv[t] = *(const float4*)&rp[t * H1 + k];
#pragma unroll
        for (int kk = 0; kk < 4; kk++) {
            float4 w = *(const float4*)&wt[(k + kk) * H1 + lane * 4];
#pragma unroll
            for (int t = 0; t < 8; t++) {
                float v = rv[t][kk];
                acc[t].x = fmaf(v, w.x, acc[t].x);
                acc[t].y = fmaf(v, w.y, acc[t].y);
                acc[t].z = fmaf(v, w.z, acc[t].z);
                acc[t].w = fmaf(v, w.w, acc[t].w);
            }
        }
    }
#pragma unroll
    for (int t = 0; t < 8; t++) {
        int n = nb + warp * 8 + t;
        if (n < NN) {
            float4 a = acc[t];
            a.x = gelu_f(a.x); a.y = gelu_f(a.y);
            a.z = gelu_f(a.z); a.w = gelu_f(a.w);
            *(float4*)&g_h1[n * H1 + lane * 4] = a;
        }
    }
}

// ---------------- gemm2: g_h2 = normalize(gelu(g_s1 @ W.T + b)) ----------------
__global__ void __launch_bounds__(256) k_gemm2(const float* __restrict__ W,
                                               const float* __restrict__ b,
                                               float* __restrict__ out_h) {
    extern __shared__ float sm[];
    float* wt = sm;                  // [128][64] transposed (32 KB)
    float* as = sm + H1 * H2;        // [64][128] (32 KB)
    int tid = threadIdx.x;
    for (int i = tid; i < H2 * H1; i += 256) {
        int o = i >> 7, k = i & 127;
        wt[k * H2 + o] = W[i];
    }
    int nb = blockIdx.x * TPB;
    for (int i = tid; i < TPB * H1 / 4; i += 256) {
        int row = (i * 4) >> 7;
        int k   = (i * 4) & 127;
        int n = nb + row;
        float4 v = (n < NN) ? *(const float4*)&g_s1[n * H1 + k]
                            : make_float4(0.f, 0.f, 0.f, 0.f);
        *(float4*)&as[row * H1 + k] = v;
    }
    __syncthreads();
    int warp = tid >> 5, lane = tid & 31;
    float2 bias = *(const float2*)&b[lane * 2];
    float2 acc[8];
#pragma unroll
    for (int t = 0; t < 8; t++) acc[t] = bias;
    const float* rp = &as[warp * 8 * H1];
    for (int k = 0; k < H1; k += 4) {
        float rv[8][4];
#pragma unroll
        for (int t = 0; t < 8; t++)
            *(float4*)rv[t] = *(const float4*)&rp[t * H1 + k];
#pragma unroll
        for (int kk = 0; kk < 4; kk++) {
            float2 w = *(const float2*)&wt[(k + kk) * H2 + lane * 2];
#pragma unroll
            for (int t = 0; t < 8; t++) {
                float v = rv[t][kk];
                acc[t].x = fmaf(v, w.x, acc[t].x);
                acc[t].y = fmaf(v, w.y, acc[t].y);
            }
        }
    }
#pragma unroll
    for (int t = 0; t < 8; t++) {
        int n = nb + warp * 8 + t;
        if (n < NN) {
            float2 a = acc[t];
            a.x = gelu_f(a.x);
            a.y = gelu_f(a.y);
            float ssq = a.x * a.x + a.y * a.y;
#pragma unroll
            for (int off = 16; off; off >>= 1) ssq += __shfl_xor_sync(0xFFFFFFFFu, ssq, off);
            float inv = 1.0f / fmaxf(sqrtf(ssq), 1e-12f);
            a.x *= inv; a.y *= inv;
            *(float2*)&g_h2[n * H2 + lane * 2] = a;
            if (out_h) *(float2*)&out_h[n * H2 + lane * 2] = a;
        }
    }
}

// ---------------- fused Set2Set + final MLP, graph h2 cached in smem ----------------
__global__ void __launch_bounds__(256) k_s2s(
        const float* __restrict__ Wih0, const float* __restrict__ Whh0,
        const float* __restrict__ bih0, const float* __restrict__ bhh0,
        const float* __restrict__ Wih1, const float* __restrict__ Whh1,
        const float* __restrict__ bih1, const float* __restrict__ bhh1,
        const float* __restrict__ fc1W, const float* __restrict__ fc1b,
        const float* __restrict__ fc2W, const float* __restrict__ fc2b,
        float* __restrict__ z) {
    extern __shared__ float dyn[];
    float* cache = dyn;                 // [S2SCAP][H2]
    float* esm   = dyn + S2SCAP * H2;   // [S2SCAP]
    __shared__ float h0[H2], c0[H2], h1[H2], c1[H2], qs[2 * H2];
    __shared__ float gb[4 * H2], red[8], rbuf[8 * H2];
    __shared__ float smax, ssum;
    int g = blockIdx.x;
    int tid = threadIdx.x, warp = tid >> 5, lane = tid & 31;
    int gs = g_gs[g], ge = g_gs[g + 1];
    int nv = ge - gs;
    const float* hp;
    float* ep;
    if (nv <= S2SCAP) {
        const float4* s4 = (const float4*)&g_h2[gs * H2];
        float4* d4 = (float4*)cache;
        int tot = nv * (H2 / 4);
        for (int i = tid; i < tot; i += 256) d4[i] = s4[i];
        hp = cache; ep = esm;
    } else {
        hp = &g_h2[gs * H2]; ep = &g_e[gs];
    }
    if (tid < H2) { h0[tid] = 0.0f; c0[tid] = 0.0f; h1[tid] = 0.0f; c1[tid] = 0.0f; }
    if (tid < 2 * H2) qs[tid] = 0.0f;
    __syncthreads();

    for (int step = 0; step < 4; step++) {
        for (int r = warp; r < 4 * H2; r += 8) {
            const float* wi = &Wih0[r * 2 * H2];
            float p = wi[lane] * qs[lane] + wi[lane + 32] * qs[lane + 32]
                    + wi[lane + 64] * qs[lane + 64] + wi[lane + 96] * qs[lane + 96];
            const float* wh = &Whh0[r * H2];
            p += wh[lane] * h0[lane] + wh[lane + 32] * h0[lane + 32];
#pragma unroll
            for (int off = 16; off; off >>= 1) p += __shfl_xor_sync(0xFFFFFFFFu, p, off);
            if (lane == 0) gb[r] = p + bih0[r] + bhh0[r];
        }
        __syncthreads();
        if (tid < H2) {
            float i = sigmoid_f(gb[tid]);
            float f = sigmoid_f(gb[H2 + tid]);
            float gg = tanhf(gb[2 * H2 + tid]);
            float o = sigmoid_f(gb[3 * H2 + tid]);
            float c = f * c0[tid] + i * gg;
            c0[tid] = c;
            h0[tid] = o * tanhf(c);
        }
        __syncthreads();
        for (int r = warp; r < 4 * H2; r += 8) {
            const float* wi = &Wih1[r * H2];
            float p = wi[lane] * h0[lane] + wi[lane + 32] * h0[lane + 32];
            const float* wh = &Whh1[r * H2];
            p += wh[lane] * h1[lane] + wh[lane + 32] * h1[lane + 32];
#pragma unroll
            for (int off = 16; off; off >>= 1) p += __shfl_xor_sync(0xFFFFFFFFu, p, off);
            if (lane == 0) gb[r] = p + bih1[r] + bhh1[r];
        }
        __syncthreads();
        if (tid < H2) {
            float i = sigmoid_f(gb[tid]);
            float f = sigmoid_f(gb[H2 + tid]);
            float gg = tanhf(gb[2 * H2 + tid]);
            float o = sigmoid_f(gb[3 * H2 + tid]);
            float c = f * c1[tid] + i * gg;
            c1[tid] = c;
            float h = o * tanhf(c);
            h1[tid] = h;
            qs[tid] = h;
        }
        __syncthreads();
        float wmax = -3.4e38f;
        for (int li = warp; li < nv; li += 8) {
            float2 hv = *(const float2*)&hp[li * H2 + lane * 2];
            float e = hv.x * qs[lane * 2] + hv.y * qs[lane * 2 + 1];
#pragma unroll
            for (int off = 16; off; off >>= 1) e += __shfl_xor_sync(0xFFFFFFFFu, e, off);
            if (lane == 0) ep[li] = e;
            wmax = fmaxf(wmax, e);
        }
        if (lane == 0) red[warp] = wmax;
        __syncthreads();
        if (tid == 0) {
            float m = red[0];
            for (int w = 1; w < 8; w++) m = fmaxf(m, red[w]);
            smax = m;
        }
        __syncthreads();
        float m = smax;
        float ps = 0.0f;
        for (int li = tid; li < nv; li += 256) {
            float ex = expf(ep[li] - m);
            ep[li] = ex;
            ps += ex;
        }
#pragma unroll
        for (int off = 16; off; off >>= 1) ps += __shfl_xor_sync(0xFFFFFFFFu, ps, off);
        if (lane == 0) red[warp] = ps;
        __syncthreads();
        if (tid == 0) {
            float s = 0.0f;
            for (int w = 0; w < 8; w++) s += red[w];
            ssum = s;
        }
        __syncthreads();
        float inv = 1.0f / (ssum + 1e-16f);
        float rx = 0.0f, ry = 0.0f;
        for (int li = warp; li < nv; li += 8) {
            float a = ep[li] * inv;
            float2 hv = *(const float2*)&hp[li * H2 + lane * 2];
            rx = fmaf(a, hv.x, rx);
            ry = fmaf(a, hv.y, ry);
        }
        rbuf[warp * H2 + lane * 2]     = rx;
        rbuf[warp * H2 + lane * 2 + 1] = ry;
        __syncthreads();
        if (tid < H2) {
            float r = 0.0f;
            for (int w = 0; w < 8; w++) r += rbuf[w * H2 + tid];
            qs[H2 + tid] = r;
        }
        __syncthreads();
    }

    for (int r = warp; r < 32; r += 8) {
        const float* wr = &fc1W[r * 2 * H2];
        float p = wr[lane] * qs[lane] + wr[lane + 32] * qs[lane + 32]
                + wr[lane + 64] * qs[lane + 64] + wr[lane + 96] * qs[lane + 96];
#pragma unroll
        for (int off = 16; off; off >>= 1) p += __shfl_xor_sync(0xFFFFFFFFu, p, off);
        if (lane == 0) gb[r] = gelu_f(p + fc1b[r]);
    }
    __syncthreads();
    if (warp == 0) {
        float v = gb[lane] * fc2W[lane];
#pragma unroll
        for (int off = 16; off; off >>= 1) v += __shfl_xor_sync(0xFFFFFFFFu, v, off);
        if (lane == 0) z[g] = v + fc2b[0];
    }
}

// ---------------- host ----------------
extern "C" void kernel_launch(void* const* d_in, const int* in_sizes, int n_in,
                              void* d_out, int out_size) {
    const float* x     = (const float*)d_in[0];
    const int*   ei    = (const int*)d_in[1];
    const int*   batch = (const int*)d_in[2];
    const float* nfcW  = (const float*)d_in[3];
    const float* nfcb  = (const float*)d_in[4];
    const float* gc1W  = (const float*)d_in[5];
    const float* gc1b  = (const float*)d_in[6];
    const float* gc2W  = (const float*)d_in[7];
    const float* gc2b  = (const float*)d_in[8];
    const float* l0Wih = (const float*)d_in[9];
    const float* l0Whh = (const float*)d_in[10];
    const float* l0bih = (const float*)d_in[11];
    const float* l0bhh = (const float*)d_in[12];
    const float* l1Wih = (const float*)d_in[13];
    const float* l1Whh = (const float*)d_in[14];
    const float* l1bih = (const float*)d_in[15];
    const float* l1bhh = (const float*)d_in[16];
    const float* fc1W  = (const float*)d_in[17];
    const float* fc1b  = (const float*)d_in[18];
    const float* fc2W  = (const float*)d_in[19];
    const float* fc2b  = (const float*)d_in[20];

    float* out = (float*)d_out;
    float* out_h = (out_size >= NG + NN * H2) ? (out + NG) : nullptr;

    int nblk = (NN + TPB - 1) / TPB;                      // 1563
    int gblk = (NN * 32 + 255) / 256;                     // 12500
    size_t sm_nfc   = (size_t)(NF * H1 + TPB * NF) * 4;   // 48 KB
    size_t sm_gemm1 = (size_t)(H1 * H1 + TPB * H1) * 4;   // 96 KB
    size_t sm_gemm2 = (size_t)(H1 * H2 + TPB * H1) * 4;   // 64 KB
    size_t sm_s2s   = (size_t)(S2SCAP * H2 + S2SCAP) * 4; // 83.2 KB
    cudaFuncSetAttribute(k_nfc,   cudaFuncAttributeMaxDynamicSharedMemorySize, (int)sm_nfc);
    cudaFuncSetAttribute(k_gemm1, cudaFuncAttributeMaxDynamicSharedMemorySize, (int)sm_gemm1);
    cudaFuncSetAttribute(k_gemm2, cudaFuncAttributeMaxDynamicSharedMemorySize, (int)sm_gemm2);
    cudaFuncSetAttribute(k_s2s,   cudaFuncAttributeMaxDynamicSharedMemorySize, (int)sm_s2s);

    k_zero<<<128, 256>>>();
    k_nfc<<<nblk, 256, sm_nfc>>>(x, nfcW, nfcb, ei);
    k_scan<<<SCB, 256>>>(batch);
    k_scatter<<<(NE + 255) / 256, 256>>>(ei);
    // conv1: gather (g_h1 -> g_s1), gemm (g_s1 -> g_h1)
    k_gather<<<gblk, 256>>>();
    k_gemm1<<<nblk, 256, sm_gemm1>>>(gc1W, gc1b);
    // conv2: gather (g_h1 -> g_s1), gemm (g_s1 -> g_h2)
    k_gather<<<gblk, 256>>>();
    k_gemm2<<<nblk, 256, sm_gemm2>>>(gc2W, gc2b, out_h);
    k_s2s<<<NG, 256, sm_s2s>>>(l0Wih, l0Whh, l0bih, l0bhh,
                               l1Wih, l1Whh, l1bih, l1bhh,
                               fc1W, fc1b, fc2W, fc2b, out);
}

// round 14
// speedup vs baseline: 1.2561x; 1.0937x over previous
#include <cuda_runtime.h>
#include <math.h>

#define NN 100000
#define NE 1600000
#define NG 512
#define NF 64
#define H1 128
#define H2 64
#define SCB 98            // scan blocks: ceil(NN/1024)
#define TPB 64            // nodes per block in dense kernels

// ---------------- device scratch ----------------
__device__ float g_h1[NN * H1];
__device__ float g_s1[NN * H1];
__device__ float g_h2[NN * H2];
__device__ float g_e[NN];
__device__ int   g_cnt[NN];
__device__ int   g_off[NN + 1];
__device__ int   g_cur[NN];
__device__ int   g_csr[NE];
__device__ int   g_gs[NG + 1];
__device__ int   g_sagg[SCB];
__device__ int   g_sflag[SCB];

__device__ __forceinline__ float gelu_f(float x) {
    return 0.5f * x * (1.0f + erff(x * 0.70710678118654752f));
}
__device__ __forceinline__ float sigmoid_f(float x) {
    return 1.0f / (1.0f + expf(-x));
}

// ---------------- init ----------------
__global__ void __launch_bounds__(256) k_zero() {
    int i = blockIdx.x * blockDim.x + threadIdx.x;
    int T = gridDim.x * blockDim.x;
    for (int j = i; j < NN; j += T) { g_cnt[j] = 0; g_cur[j] = 0; }
    if (i < SCB) { g_sflag[i] = 0; g_sagg[i] = 0; }
    if (i == 0) g_off[NN] = NE;
}

// ---------------- nfc (64 nodes/block) + edge counting fold ----------------
__global__ void __launch_bounds__(256) k_nfc(const float* __restrict__ x,
                                             const float* __restrict__ W,
                                             const float* __restrict__ b,
                                             const int* __restrict__ ei) {
    extern __shared__ float sm[];
    float* wt = sm;                  // [64][128] transposed (32 KB)
    float* xs = sm + NF * H1;        // [64][64]  (16 KB)
    int tid = threadIdx.x;
    {
        int eb = blockIdx.x * 1024 + tid * 4;
#pragma unroll
        for (int i = 0; i < 4; i++)
            if (eb + i < NE) atomicAdd(&g_cnt[ei[NE + eb + i]], 1);
    }
    for (int i = tid; i < H1 * NF; i += 256) {
        int o = i >> 6, k = i & 63;
        wt[k * H1 + o] = W[i];
    }
    int warp = tid >> 5, lane = tid & 31;
    int nb = blockIdx.x * TPB;
#pragma unroll
    for (int t = 0; t < 8; t++) {
        int row = warp * 8 + t;
        int n = nb + row;
        if (n < NN) {
            float2 xv = *(const float2*)&x[n * NF + lane * 2];
            *(float2*)&xs[row * NF + lane * 2] = xv;
        }
    }
    __syncthreads();
    float4 bias = *(const float4*)&b[lane * 4];
    float4 acc[8];
#pragma unroll
    for (int t = 0; t < 8; t++) acc[t] = bias;
    const float* rp = &xs[warp * 8 * NF];
#pragma unroll 4
    for (int k = 0; k < NF; k++) {
        float4 w = *(const float4*)&wt[k * H1 + lane * 4];
#pragma unroll
        for (int t = 0; t < 8; t++) {
            float v = rp[t * NF + k];
            acc[t].x = fmaf(v, w.x, acc[t].x);
            acc[t].y = fmaf(v, w.y, acc[t].y);
            acc[t].z = fmaf(v, w.z, acc[t].z);
            acc[t].w = fmaf(v, w.w, acc[t].w);
        }
    }
#pragma unroll
    for (int t = 0; t < 8; t++) {
        int n = nb + warp * 8 + t;
        if (n < NN) {
            float4 a = acc[t];
            a.x = gelu_f(a.x); a.y = gelu_f(a.y);
            a.z = gelu_f(a.z); a.w = gelu_f(a.w);
            *(float4*)&g_h1[n * H1 + lane * 4] = a;
        }
    }
}

// ---------------- single-pass scan (decoupled lookback) + gstart fold ----------------
__global__ void __launch_bounds__(256) k_scan(const int* __restrict__ batch) {
    __shared__ int sm[256];
    __shared__ int addsh;
    int tid = threadIdx.x;
    int b = blockIdx.x;
    if (tid == 0) addsh = 0;
    int idx = b * 1024 + tid * 4;
    int v0 = 0, v1 = 0, v2 = 0, v3 = 0;
    if (idx     < NN) v0 = g_cnt[idx];
    if (idx + 1 < NN) v1 = g_cnt[idx + 1];
    if (idx + 2 < NN) v2 = g_cnt[idx + 2];
    if (idx + 3 < NN) v3 = g_cnt[idx + 3];
    int t = v0 + v1 + v2 + v3;
    sm[tid] = t;
    __syncthreads();
    for (int off = 1; off < 256; off <<= 1) {
        int u = (tid >= off) ? sm[tid - off] : 0;
        __syncthreads();
        sm[tid] += u;
        __syncthreads();
    }
    if (tid == 0) {
        g_sagg[b] = sm[255];
        __threadfence();
        atomicExch(&g_sflag[b], 1);
    }
    int excl = sm[tid] - t;
    int myadd = 0;
    for (int i = tid; i < b; i += 256) {
        while (((volatile int*)g_sflag)[i] == 0) { }
        myadd += ((volatile int*)g_sagg)[i];
    }
#pragma unroll
    for (int off = 16; off; off >>= 1) myadd += __shfl_xor_sync(0xFFFFFFFFu, myadd, off);
    if ((tid & 31) == 0 && myadd) atomicAdd(&addsh, myadd);
    __syncthreads();
    int add = addsh;
    if (idx     < NN) g_off[idx]     = excl + add;
    if (idx + 1 < NN) g_off[idx + 1] = excl + add + v0;
    if (idx + 2 < NN) g_off[idx + 2] = excl + add + v0 + v1;
    if (idx + 3 < NN) g_off[idx + 3] = excl + add + v0 + v1 + v2;
#pragma unroll
    for (int i = 0; i < 4; i++) {
        int n = idx + i;
        if (n < NN) {
            int bb = batch[n];
            int bp = (n == 0) ? -1 : batch[n - 1];
            for (int g = bp + 1; g <= bb; g++) g_gs[g] = n;
            if (n == NN - 1)
                for (int g = bb + 1; g <= NG; g++) g_gs[g] = NN;
        }
    }
}

__global__ void __launch_bounds__(256) k_scatter(const int* __restrict__ ei) {
    int e = blockIdx.x * blockDim.x + threadIdx.x;
    if (e < NE) {
        int s = ei[e];
        int d = ei[NE + e];
        int pos = atomicAdd(&g_cur[d], 1);
        g_csr[g_off[d] + pos] = s;
    }
}

// ---------------- gather: warp per node, g_h1 -> g_s1 (128-d) ----------------
__global__ void __launch_bounds__(256) k_gather() {
    int n = (blockIdx.x * 256 + threadIdx.x) >> 5;
    int lane = threadIdx.x & 31;
    if (n >= NN) return;
    const float* src = g_h1;
    float4 a = *(const float4*)&src[n * H1 + lane * 4];
    int e0 = g_off[n], e1 = g_off[n + 1];
    int j = e0;
    for (; j + 7 < e1; j += 8) {
        int s0 = g_csr[j],     s1 = g_csr[j + 1], s2 = g_csr[j + 2], s3 = g_csr[j + 3];
        int s4 = g_csr[j + 4], s5 = g_csr[j + 5], s6 = g_csr[j + 6], s7 = g_csr[j + 7];
        float4 v0 = *(const float4*)&src[s0 * H1 + lane * 4];
        float4 v1 = *(const float4*)&src[s1 * H1 + lane * 4];
        float4 v2 = *(const float4*)&src[s2 * H1 + lane * 4];
        float4 v3 = *(const float4*)&src[s3 * H1 + lane * 4];
        float4 v4 = *(const float4*)&src[s4 * H1 + lane * 4];
        float4 v5 = *(const float4*)&src[s5 * H1 + lane * 4];
        float4 v6 = *(const float4*)&src[s6 * H1 + lane * 4];
        float4 v7 = *(const float4*)&src[s7 * H1 + lane * 4];
        a.x += ((v0.x + v1.x) + (v2.x + v3.x)) + ((v4.x + v5.x) + (v6.x + v7.x));
        a.y += ((v0.y + v1.y) + (v2.y + v3.y)) + ((v4.y + v5.y) + (v6.y + v7.y));
        a.z += ((v0.z + v1.z) + (v2.z + v3.z)) + ((v4.z + v5.z) + (v6.z + v7.z));
        a.w += ((v0.w + v1.w) + (v2.w + v3.w)) + ((v4.w + v5.w) + (v6.w + v7.w));
    }
    if (j + 3 < e1) {
        int s0 = g_csr[j], s1 = g_csr[j + 1], s2 = g_csr[j + 2], s3 = g_csr[j + 3];
        float4 v0 = *(const float4*)&src[s0 * H1 + lane * 4];
        float4 v1 = *(const float4*)&src[s1 * H1 + lane * 4];
        float4 v2 = *(const float4*)&src[s2 * H1 + lane * 4];
        float4 v3 = *(const float4*)&src[s3 * H1 + lane * 4];
        a.x += (v0.x + v1.x) + (v2.x + v3.x);
        a.y += (v0.y + v1.y) + (v2.y + v3.y);
        a.z += (v0.z + v1.z) + (v2.z + v3.z);
        a.w += (v0.w + v1.w) + (v2.w + v3.w);
        j += 4;
    }
    for (; j < e1; j++) {
        int s0 = g_csr[j];
        float4 v0 = *(const float4*)&src[s0 * H1 + lane * 4];
        a.x += v0.x; a.y += v0.y; a.z += v0.z; a.w += v0.w;
    }
    *(float4*)&g_s1[n * H1 + lane * 4] = a;
}

// ---------------- gemm1: g_h1 = gelu(g_s1 @ W.T + b) ----------------
__global__ void __launch_bounds__(256) k_gemm1(const float* __restrict__ W,
                                               const float* __restrict__ b) {
    extern __shared__ float sm[];
    float* wt = sm;                  // [128][128] transposed (64 KB)
    float* as = sm + H1 * H1;        // [64][128] (32 KB)
    int tid = threadIdx.x;
    for (int i = tid; i < H1 * H1; i += 256) {
        int o = i >> 7, k = i & 127;
        wt[k * H1 + o] = W[i];
    }
    int nb = blockIdx.x * TPB;
    for (int i = tid; i < TPB * H1 / 4; i += 256) {
        int row = (i * 4) >> 7;
        int k   = (i * 4) & 127;
        int n = nb + row;
        float4 v = (n < NN) ? *(const float4*)&g_s1[n * H1 + k]
                            : make_float4(0.f, 0.f, 0.f, 0.f);
        *(float4*)&as[row * H1 + k] = v;
    }
    __syncthreads();
    int warp = tid >> 5, lane = tid & 31;
    float4 bias = *(const float4*)&b[lane * 4];
    float4 acc[8];
#pragma unroll
    for (int t = 0; t < 8; t++) acc[t] = bias;
    const float* rp = &as[warp * 8 * H1];
#pragma unroll 4
    for (int k = 0; k < H1; k++) {
        float4 w = *(const float4*)&wt[k * H1 + lane * 4];
#pragma unroll
        for (int t = 0; t < 8; t++) {
            float v = rp[t * H1 + k];
            acc[t].x = fmaf(v, w.x, acc[t].x);
            acc[t].y = fmaf(v, w.y, acc[t].y);
            acc[t].z = fmaf(v, w.z, acc[t].z);
            acc[t].w = fmaf(v, w.w, acc[t].w);
        }
    }
#pragma unroll
    for (int t = 0; t < 8; t++) {
        int n = nb + warp * 8 + t;
        if (n < NN) {
            float4 a = acc[t];
            a.x = gelu_f(a.x); a.y = gelu_f(a.y);
            a.z = gelu_f(a.z); a.w = gelu_f(a.w);
            *(float4*)&g_h1[n * H1 + lane * 4] = a;
        }
    }
}

// ---------------- gemm2t: g_s1(64-d) = g_h1 @ W2.T (linear only, no bias/act) ----------------
__global__ void __launch_bounds__(256) k_gemm2t(const float* __restrict__ W) {
    extern __shared__ float sm[];
    float* wt = sm;                  // [128][64] transposed (32 KB)
    float* as = sm + H1 * H2;        // [64][128] (32 KB)
    int tid = threadIdx.x;
    for (int i = tid; i < H2 * H1; i += 256) {
        int o = i >> 7, k = i & 127;
        wt[k * H2 + o] = W[i];
    }
    int nb = blockIdx.x * TPB;
    for (int i = tid; i < TPB * H1 / 4; i += 256) {
        int row = (i * 4) >> 7;
        int k   = (i * 4) & 127;
        int n = nb + row;
        float4 v = (n < NN) ? *(const float4*)&g_h1[n * H1 + k]
                            : make_float4(0.f, 0.f, 0.f, 0.f);
        *(float4*)&as[row * H1 + k] = v;
    }
    __syncthreads();
    int warp = tid >> 5, lane = tid & 31;
    float2 acc[8];
#pragma unroll
    for (int t = 0; t < 8; t++) acc[t] = make_float2(0.f, 0.f);
    const float* rp = &as[warp * 8 * H1];
#pragma unroll 4
    for (int k = 0; k < H1; k++) {
        float2 w = *(const float2*)&wt[k * H2 + lane * 2];
#pragma unroll
        for (int t = 0; t < 8; t++) {
            float v = rp[t * H1 + k];
            acc[t].x = fmaf(v, w.x, acc[t].x);
            acc[t].y = fmaf(v, w.y, acc[t].y);
        }
    }
#pragma unroll
    for (int t = 0; t < 8; t++) {
        int n = nb + warp * 8 + t;
        if (n < NN)
            *(float2*)&g_s1[n * H2 + lane * 2] = acc[t];
    }
}

// ---------------- gather64: agg z2 (64-d), +b2, gelu, normalize -> g_h2/out_h ----------------
__global__ void __launch_bounds__(256) k_gather64(const float* __restrict__ b2,
                                                  float* __restrict__ out_h) {
    int n = (blockIdx.x * 256 + threadIdx.x) >> 5;
    int lane = threadIdx.x & 31;
    if (n >= NN) return;
    const float* src = g_s1;   // 64-d z2
    float2 a = *(const float2*)&src[n * H2 + lane * 2];
    int e0 = g_off[n], e1 = g_off[n + 1];
    int j = e0;
    for (; j + 15 < e1; j += 16) {
        float2 v[16];
#pragma unroll
        for (int u = 0; u < 16; u++) {
            int s = g_csr[j + u];
            v[u] = *(const float2*)&src[s * H2 + lane * 2];
        }
        float sx = 0.f, sy = 0.f;
#pragma unroll
        for (int u = 0; u < 16; u++) { sx += v[u].x; sy += v[u].y; }
        a.x += sx; a.y += sy;
    }
    if (j + 7 < e1) {
        float2 v[8];
#pragma unroll
        for (int u = 0; u < 8; u++) {
            int s = g_csr[j + u];
            v[u] = *(const float2*)&src[s * H2 + lane * 2];
        }
        float sx = 0.f, sy = 0.f;
#pragma unroll
        for (int u = 0; u < 8; u++) { sx += v[u].x; sy += v[u].y; }
        a.x += sx; a.y += sy;
        j += 8;
    }
    for (; j < e1; j++) {
        int s = g_csr[j];
        float2 v = *(const float2*)&src[s * H2 + lane * 2];
        a.x += v.x; a.y += v.y;
    }
    float2 bb = *(const float2*)&b2[lane * 2];
    a.x = gelu_f(a.x + bb.x);
    a.y = gelu_f(a.y + bb.y);
    float ssq = a.x * a.x + a.y * a.y;
#pragma unroll
    for (int off = 16; off; off >>= 1) ssq += __shfl_xor_sync(0xFFFFFFFFu, ssq, off);
    float inv = 1.0f / fmaxf(sqrtf(ssq), 1e-12f);
    a.x *= inv; a.y *= inv;
    *(float2*)&g_h2[n * H2 + lane * 2] = a;
    if (out_h) *(float2*)&out_h[n * H2 + lane * 2] = a;
}

// ---------------- fused Set2Set (4 steps) + final MLP: one block per graph ----------------
__global__ void __launch_bounds__(256) k_s2s(
        const float* __restrict__ Wih0, const float* __restrict__ Whh0,
        const float* __restrict__ bih0, const float* __restrict__ bhh0,
        const float* __restrict__ Wih1, const float* __restrict__ Whh1,
        const float* __restrict__ bih1, const float* __restrict__ bhh1,
        const float* __restrict__ fc1W, const float* __restrict__ fc1b,
        const float* __restrict__ fc2W, const float* __restrict__ fc2b,
        float* __restrict__ z) {
    __shared__ float h0[H2], c0[H2], h1[H2], c1[H2], qs[2 * H2];
    __shared__ float gb[4 * H2], red[8], rbuf[8 * H2];
    __shared__ float smax, ssum;
    int g = blockIdx.x;
    int tid = threadIdx.x, warp = tid >> 5, lane = tid & 31;
    int gs = g_gs[g], ge = g_gs[g + 1];
    if (tid < H2) { h0[tid] = 0.0f; c0[tid] = 0.0f; h1[tid] = 0.0f; c1[tid] = 0.0f; }
    if (tid < 2 * H2) qs[tid] = 0.0f;
    __syncthreads();

    for (int step = 0; step < 4; step++) {
        for (int r = warp; r < 4 * H2; r += 8) {
            const float* wi = &Wih0[r * 2 * H2];
            float p = wi[lane] * qs[lane] + wi[lane + 32] * qs[lane + 32]
                    + wi[lane + 64] * qs[lane + 64] + wi[lane + 96] * qs[lane + 96];
            const float* wh = &Whh0[r * H2];
            p += wh[lane] * h0[lane] + wh[lane + 32] * h0[lane + 32];
#pragma unroll
            for (int off = 16; off; off >>= 1) p += __shfl_xor_sync(0xFFFFFFFFu, p, off);
            if (lane == 0) gb[r] = p + bih0[r] + bhh0[r];
        }
        __syncthreads();
        if (tid < H2) {
            float i = sigmoid_f(gb[tid]);
            float f = sigmoid_f(gb[H2 + tid]);
            float gg = tanhf(gb[2 * H2 + tid]);
            float o = sigmoid_f(gb[3 * H2 + tid]);
            float c = f * c0[tid] + i * gg;
            c0[tid] = c;
            h0[tid] = o * tanhf(c);
        }
        __syncthreads();
        for (int r = warp; r < 4 * H2; r += 8) {
            const float* wi = &Wih1[r * H2];
            float p = wi[lane] * h0[lane] + wi[lane + 32] * h0[lane + 32];
            const float* wh = &Whh1[r * H2];
            p += wh[lane] * h1[lane] + wh[lane + 32] * h1[lane + 32];
#pragma unroll
            for (int off = 16; off; off >>= 1) p += __shfl_xor_sync(0xFFFFFFFFu, p, off);
            if (lane == 0) gb[r] = p + bih1[r] + bhh1[r];
        }
        __syncthreads();
        if (tid < H2) {
            float i = sigmoid_f(gb[tid]);
            float f = sigmoid_f(gb[H2 + tid]);
            float gg = tanhf(gb[2 * H2 + tid]);
            float o = sigmoid_f(gb[3 * H2 + tid]);
            float c = f * c1[tid] + i * gg;
            c1[tid] = c;
            float h = o * tanhf(c);
            h1[tid] = h;
            qs[tid] = h;
        }
        __syncthreads();
        float wmax = -3.4e38f;
        for (int n = gs + warp; n < ge; n += 8) {
            float2 hv = *(const float2*)&g_h2[n * H2 + lane * 2];
            float e = hv.x * qs[lane * 2] + hv.y * qs[lane * 2 + 1];
#pragma unroll
            for (int off = 16; off; off >>= 1) e += __shfl_xor_sync(0xFFFFFFFFu, e, off);
            if (lane == 0) g_e[n] = e;
            wmax = fmaxf(wmax, e);
        }
        if (lane == 0) red[warp] = wmax;
        __syncthreads();
        if (tid == 0) {
            float m = red[0];
            for (int w = 1; w < 8; w++) m = fmaxf(m, red[w]);
            smax = m;
        }
        __syncthreads();
        float m = smax;
        float ps = 0.0f;
        for (int n = gs + tid; n < ge; n += 256) {
            float ex = expf(g_e[n] - m);
            g_e[n] = ex;
            ps += ex;
        }
#pragma unroll
        for (int off = 16; off; off >>= 1) ps += __shfl_xor_sync(0xFFFFFFFFu, ps, off);
        if (lane == 0) red[warp] = ps;
        __syncthreads();
        if (tid == 0) {
            float s = 0.0f;
            for (int w = 0; w < 8; w++) s += red[w];
            ssum = s;
        }
        __syncthreads();
        float inv = 1.0f / (ssum + 1e-16f);
        float rx = 0.0f, ry = 0.0f;
        for (int n = gs + warp; n < ge; n += 8) {
            float a = g_e[n] * inv;
            float2 hv = *(const float2*)&g_h2[n * H2 + lane * 2];
            rx = fmaf(a, hv.x, rx);
            ry = fmaf(a, hv.y, ry);
        }
        rbuf[warp * H2 + lane * 2]     = rx;
        rbuf[warp * H2 + lane * 2 + 1] = ry;
        __syncthreads();
        if (tid < H2) {
            float r = 0.0f;
            for (int w = 0; w < 8; w++) r += rbuf[w * H2 + tid];
            qs[H2 + tid] = r;
        }
        __syncthreads();
    }

    for (int r = warp; r < 32; r += 8) {
        const float* wr = &fc1W[r * 2 * H2];
        float p = wr[lane] * qs[lane] + wr[lane + 32] * qs[lane + 32]
                + wr[lane + 64] * qs[lane + 64] + wr[lane + 96] * qs[lane + 96];
#pragma unroll
        for (int off = 16; off; off >>= 1) p += __shfl_xor_sync(0xFFFFFFFFu, p, off);
        if (lane == 0) gb[r] = gelu_f(p + fc1b[r]);
    }
    __syncthreads();
    if (warp == 0) {
        float v = gb[lane] * fc2W[lane];
#pragma unroll
        for (int off = 16; off; off >>= 1) v += __shfl_xor_sync(0xFFFFFFFFu, v, off);
        if (lane == 0) z[g] = v + fc2b[0];
    }
}

// ---------------- host ----------------
extern "C" void kernel_launch(void* const* d_in, const int* in_sizes, int n_in,
                              void* d_out, int out_size) {
    const float* x     = (const float*)d_in[0];
    const int*   ei    = (const int*)d_in[1];
    const int*   batch = (const int*)d_in[2];
    const float* nfcW  = (const float*)d_in[3];
    const float* nfcb  = (const float*)d_in[4];
    const float* gc1W  = (const float*)d_in[5];
    const float* gc1b  = (const float*)d_in[6];
    const float* gc2W  = (const float*)d_in[7];
    const float* gc2b  = (const float*)d_in[8];
    const float* l0Wih = (const float*)d_in[9];
    const float* l0Whh = (const float*)d_in[10];
    const float* l0bih = (const float*)d_in[11];
    const float* l0bhh = (const float*)d_in[12];
    const float* l1Wih = (const float*)d_in[13];
    const float* l1Whh = (const float*)d_in[14];
    const float* l1bih = (const float*)d_in[15];
    const float* l1bhh = (const float*)d_in[16];
    const float* fc1W  = (const float*)d_in[17];
    const float* fc1b  = (const float*)d_in[18];
    const float* fc2W  = (const float*)d_in[19];
    const float* fc2b  = (const float*)d_in[20];

    float* out = (float*)d_out;
    float* out_h = (out_size >= NG + NN * H2) ? (out + NG) : nullptr;

    int nblk = (NN + TPB - 1) / TPB;                      // 1563
    int gblk = (NN * 32 + 255) / 256;                     // 12500
    size_t sm_nfc   = (size_t)(NF * H1 + TPB * NF) * 4;   // 48 KB
    size_t sm_gemm1 = (size_t)(H1 * H1 + TPB * H1) * 4;   // 96 KB
    size_t sm_gemm2 = (size_t)(H1 * H2 + TPB * H1) * 4;   // 64 KB
    cudaFuncSetAttribute(k_nfc,    cudaFuncAttributeMaxDynamicSharedMemorySize, (int)sm_nfc);
    cudaFuncSetAttribute(k_gemm1,  cudaFuncAttributeMaxDynamicSharedMemorySize, (int)sm_gemm1);
    cudaFuncSetAttribute(k_gemm2t, cudaFuncAttributeMaxDynamicSharedMemorySize, (int)sm_gemm2);

    k_zero<<<128, 256>>>();
    k_nfc<<<nblk, 256, sm_nfc>>>(x, nfcW, nfcb, ei);
    k_scan<<<SCB, 256>>>(batch);
    k_scatter<<<(NE + 255) / 256, 256>>>(ei);
    // conv1: gather (g_h1 -> g_s1, 128-d), gemm (g_s1 -> g_h1)
    k_gather<<<gblk, 256>>>();
    k_gemm1<<<nblk, 256, sm_gemm1>>>(gc1W, gc1b);
    // conv2 via linearity: dense z2 = W2*h_mid first, then 64-d aggregate
    k_gemm2t<<<nblk, 256, sm_gemm2>>>(gc2W);
    k_gather64<<<gblk, 256>>>(gc2b, out_h);
    k_s2s<<<NG, 256>>>(l0Wih, l0Whh, l0bih, l0bhh,
                       l1Wih, l1Whh, l1bih, l1bhh,
                       fc1W, fc1b, fc2W, fc2b, out);
}

// round 15
// speedup vs baseline: 1.3136x; 1.0458x over previous
#include <cuda_runtime.h>
#include <math.h>

#define NN 100000
#define NE 1600000
#define NG 512
#define NF 64
#define H1 128
#define H2 64
#define SCB 98            // scan blocks: ceil(NN/1024)
#define TPB 64            // nodes per block in dense kernels

// ---------------- device scratch ----------------
__device__ float g_h1[NN * H1];
__device__ float g_s1[NN * H1];
__device__ float g_h2[NN * H2];
__device__ float g_e[NN];
__device__ int   g_cnt[NN];
__device__ int   g_off[NN + 1];
__device__ int   g_cur[NN];
__device__ int   g_csr[NE];
__device__ int   g_gs[NG + 1];
__device__ int   g_sagg[SCB];
__device__ int   g_sflag[SCB];

__device__ __forceinline__ float gelu_f(float x) {
    return 0.5f * x * (1.0f + erff(x * 0.70710678118654752f));
}
__device__ __forceinline__ float sigmoid_f(float x) {
    return 1.0f / (1.0f + expf(-x));
}

// ---------------- init ----------------
__global__ void __launch_bounds__(256) k_zero() {
    int i = blockIdx.x * blockDim.x + threadIdx.x;
    int T = gridDim.x * blockDim.x;
    for (int j = i; j < NN; j += T) { g_cnt[j] = 0; g_cur[j] = 0; }
    if (i < SCB) { g_sflag[i] = 0; g_sagg[i] = 0; }
    if (i == 0) g_off[NN] = NE;
}

// ---------------- nfc (64 nodes/block) + edge counting fold ----------------
__global__ void __launch_bounds__(256) k_nfc(const float* __restrict__ x,
                                             const float* __restrict__ W,
                                             const float* __restrict__ b,
                                             const int* __restrict__ ei) {
    extern __shared__ float sm[];
    float* wt = sm;                  // [64][128] transposed (32 KB)
    float* xs = sm + NF * H1;        // [64][64]  (16 KB)
    int tid = threadIdx.x;
    {
        int eb = blockIdx.x * 1024 + tid * 4;
#pragma unroll
        for (int i = 0; i < 4; i++)
            if (eb + i < NE) atomicAdd(&g_cnt[ei[NE + eb + i]], 1);
    }
    for (int i = tid; i < H1 * NF; i += 256) {
        int o = i >> 6, k = i & 63;
        wt[k * H1 + o] = W[i];
    }
    int warp = tid >> 5, lane = tid & 31;
    int nb = blockIdx.x * TPB;
#pragma unroll
    for (int t = 0; t < 8; t++) {
        int row = warp * 8 + t;
        int n = nb + row;
        if (n < NN) {
            float2 xv = *(const float2*)&x[n * NF + lane * 2];
            *(float2*)&xs[row * NF + lane * 2] = xv;
        }
    }
    __syncthreads();
    float4 bias = *(const float4*)&b[lane * 4];
    float4 acc[8];
#pragma unroll
    for (int t = 0; t < 8; t++) acc[t] = bias;
    const float* rp = &xs[warp * 8 * NF];
#pragma unroll 4
    for (int k = 0; k < NF; k++) {
        float4 w = *(const float4*)&wt[k * H1 + lane * 4];
#pragma unroll
        for (int t = 0; t < 8; t++) {
            float v = rp[t * NF + k];
            acc[t].x = fmaf(v, w.x, acc[t].x);
            acc[t].y = fmaf(v, w.y, acc[t].y);
            acc[t].z = fmaf(v, w.z, acc[t].z);
            acc[t].w = fmaf(v, w.w, acc[t].w);
        }
    }
#pragma unroll
    for (int t = 0; t < 8; t++) {
        int n = nb + warp * 8 + t;
        if (n < NN) {
            float4 a = acc[t];
            a.x = gelu_f(a.x); a.y = gelu_f(a.y);
            a.z = gelu_f(a.z); a.w = gelu_f(a.w);
            *(float4*)&g_h1[n * H1 + lane * 4] = a;
        }
    }
}

// ---------------- single-pass scan (decoupled lookback) + gstart fold ----------------
__global__ void __launch_bounds__(256) k_scan(const int* __restrict__ batch) {
    __shared__ int sm[256];
    __shared__ int addsh;
    int tid = threadIdx.x;
    int b = blockIdx.x;
    if (tid == 0) addsh = 0;
    int idx = b * 1024 + tid * 4;
    int v0 = 0, v1 = 0, v2 = 0, v3 = 0;
    if (idx     < NN) v0 = g_cnt[idx];
    if (idx + 1 < NN) v1 = g_cnt[idx + 1];
    if (idx + 2 < NN) v2 = g_cnt[idx + 2];
    if (idx + 3 < NN) v3 = g_cnt[idx + 3];
    int t = v0 + v1 + v2 + v3;
    sm[tid] = t;
    __syncthreads();
    for (int off = 1; off < 256; off <<= 1) {
        int u = (tid >= off) ? sm[tid - off] : 0;
        __syncthreads();
        sm[tid] += u;
        __syncthreads();
    }
    if (tid == 0) {
        g_sagg[b] = sm[255];
        __threadfence();
        atomicExch(&g_sflag[b], 1);
    }
    int excl = sm[tid] - t;
    int myadd = 0;
    for (int i = tid; i < b; i += 256) {
        while (((volatile int*)g_sflag)[i] == 0) { }
        myadd += ((volatile int*)g_sagg)[i];
    }
#pragma unroll
    for (int off = 16; off; off >>= 1) myadd += __shfl_xor_sync(0xFFFFFFFFu, myadd, off);
    if ((tid & 31) == 0 && myadd) atomicAdd(&addsh, myadd);
    __syncthreads();
    int add = addsh;
    if (idx     < NN) g_off[idx]     = excl + add;
    if (idx + 1 < NN) g_off[idx + 1] = excl + add + v0;
    if (idx + 2 < NN) g_off[idx + 2] = excl + add + v0 + v1;
    if (idx + 3 < NN) g_off[idx + 3] = excl + add + v0 + v1 + v2;
#pragma unroll
    for (int i = 0; i < 4; i++) {
        int n = idx + i;
        if (n < NN) {
            int bb = batch[n];
            int bp = (n == 0) ? -1 : batch[n - 1];
            for (int g = bp + 1; g <= bb; g++) g_gs[g] = n;
            if (n == NN - 1)
                for (int g = bb + 1; g <= NG; g++) g_gs[g] = NN;
        }
    }
}

__global__ void __launch_bounds__(256) k_scatter(const int* __restrict__ ei) {
    int e = blockIdx.x * blockDim.x + threadIdx.x;
    if (e < NE) {
        int s = ei[e];
        int d = ei[NE + e];
        int pos = atomicAdd(&g_cur[d], 1);
        g_csr[g_off[d] + pos] = s;
    }
}

// ---------------- gather: warp per node, g_h1 -> g_s1 (128-d) ----------------
__global__ void __launch_bounds__(256) k_gather() {
    int n = (blockIdx.x * 256 + threadIdx.x) >> 5;
    int lane = threadIdx.x & 31;
    if (n >= NN) return;
    const float* src = g_h1;
    float4 a = *(const float4*)&src[n * H1 + lane * 4];
    int e0 = g_off[n], e1 = g_off[n + 1];
    int j = e0;
    for (; j + 7 < e1; j += 8) {
        int s0 = g_csr[j],     s1 = g_csr[j + 1], s2 = g_csr[j + 2], s3 = g_csr[j + 3];
        int s4 = g_csr[j + 4], s5 = g_csr[j + 5], s6 = g_csr[j + 6], s7 = g_csr[j + 7];
        float4 v0 = *(const float4*)&src[s0 * H1 + lane * 4];
        float4 v1 = *(const float4*)&src[s1 * H1 + lane * 4];
        float4 v2 = *(const float4*)&src[s2 * H1 + lane * 4];
        float4 v3 = *(const float4*)&src[s3 * H1 + lane * 4];
        float4 v4 = *(const float4*)&src[s4 * H1 + lane * 4];
        float4 v5 = *(const float4*)&src[s5 * H1 + lane * 4];
        float4 v6 = *(const float4*)&src[s6 * H1 + lane * 4];
        float4 v7 = *(const float4*)&src[s7 * H1 + lane * 4];
        a.x += ((v0.x + v1.x) + (v2.x + v3.x)) + ((v4.x + v5.x) + (v6.x + v7.x));
        a.y += ((v0.y + v1.y) + (v2.y + v3.y)) + ((v4.y + v5.y) + (v6.y + v7.y));
        a.z += ((v0.z + v1.z) + (v2.z + v3.z)) + ((v4.z + v5.z) + (v6.z + v7.z));
        a.w += ((v0.w + v1.w) + (v2.w + v3.w)) + ((v4.w + v5.w) + (v6.w + v7.w));
    }
    if (j + 3 < e1) {
        int s0 = g_csr[j], s1 = g_csr[j + 1], s2 = g_csr[j + 2], s3 = g_csr[j + 3];
        float4 v0 = *(const float4*)&src[s0 * H1 + lane * 4];
        float4 v1 = *(const float4*)&src[s1 * H1 + lane * 4];
        float4 v2 = *(const float4*)&src[s2 * H1 + lane * 4];
        float4 v3 = *(const float4*)&src[s3 * H1 + lane * 4];
        a.x += (v0.x + v1.x) + (v2.x + v3.x);
        a.y += (v0.y + v1.y) + (v2.y + v3.y);
        a.z += (v0.z + v1.z) + (v2.z + v3.z);
        a.w += (v0.w + v1.w) + (v2.w + v3.w);
        j += 4;
    }
    for (; j < e1; j++) {
        int s0 = g_csr[j];
        float4 v0 = *(const float4*)&src[s0 * H1 + lane * 4];
        a.x += v0.x; a.y += v0.y; a.z += v0.z; a.w += v0.w;
    }
    *(float4*)&g_s1[n * H1 + lane * 4] = a;
}

// ---------------- gemmA (fused): y = gelu(agg@W1.T + b1); z2 = y@W2.T -> g_h1(64-d) ----------------
__global__ void __launch_bounds__(256) k_gemmA(const float* __restrict__ W1,
                                               const float* __restrict__ b1,
                                               const float* __restrict__ W2) {
    extern __shared__ float sm[];
    float* wt = sm;                  // phase1: [128][128] W1^T (64 KB); phase2: [128][64] W2^T (32 KB)
    float* as = sm + H1 * H1;        // [64][128] activations (32 KB)
    int tid = threadIdx.x;
    for (int i = tid; i < H1 * H1; i += 256) {
        int o = i >> 7, k = i & 127;
        wt[k * H1 + o] = W1[i];
    }
    int nb = blockIdx.x * TPB;
    for (int i = tid; i < TPB * H1 / 4; i += 256) {
        int row = (i * 4) >> 7;
        int k   = (i * 4) & 127;
        int n = nb + row;
        float4 v = (n < NN) ? *(const float4*)&g_s1[n * H1 + k]
                            : make_float4(0.f, 0.f, 0.f, 0.f);
        *(float4*)&as[row * H1 + k] = v;
    }
    __syncthreads();
    int warp = tid >> 5, lane = tid & 31;
    // ---- phase 1: y = gelu(agg @ W1.T + b1)
    {
        float4 bias = *(const float4*)&b1[lane * 4];
        float4 acc[8];
#pragma unroll
        for (int t = 0; t < 8; t++) acc[t] = bias;
        const float* rp = &as[warp * 8 * H1];
#pragma unroll 4
        for (int k = 0; k < H1; k++) {
            float4 w = *(const float4*)&wt[k * H1 + lane * 4];
#pragma unroll
            for (int t = 0; t < 8; t++) {
                float v = rp[t * H1 + k];
                acc[t].x = fmaf(v, w.x, acc[t].x);
                acc[t].y = fmaf(v, w.y, acc[t].y);
                acc[t].z = fmaf(v, w.z, acc[t].z);
                acc[t].w = fmaf(v, w.w, acc[t].w);
            }
        }
        // write y back into this warp's own rows of 'as' (exclusive ownership, no sync needed)
        float* wp = &as[warp * 8 * H1];
#pragma unroll
        for (int t = 0; t < 8; t++) {
            float4 a = acc[t];
            a.x = gelu_f(a.x); a.y = gelu_f(a.y);
            a.z = gelu_f(a.z); a.w = gelu_f(a.w);
            *(float4*)&wp[t * H1 + lane * 4] = a;
        }
    }
    __syncthreads();
    // ---- load W2^T into first 32 KB of wt
    for (int i = tid; i < H2 * H1; i += 256) {
        int o = i >> 7, k = i & 127;
        wt[k * H2 + o] = W2[i];
    }
    __syncthreads();
    // ---- phase 2: z2 = y @ W2.T (64-d out, packed into g_h1)
    {
        float2 acc[8];
#pragma unroll
        for (int t = 0; t < 8; t++) acc[t] = make_float2(0.f, 0.f);
        const float* rp = &as[warp * 8 * H1];
#pragma unroll 4
        for (int k = 0; k < H1; k++) {
            float2 w = *(const float2*)&wt[k * H2 + lane * 2];
#pragma unroll
            for (int t = 0; t < 8; t++) {
                float v = rp[t * H1 + k];
                acc[t].x = fmaf(v, w.x, acc[t].x);
                acc[t].y = fmaf(v, w.y, acc[t].y);
            }
        }
#pragma unroll
        for (int t = 0; t < 8; t++) {
            int n = nb + warp * 8 + t;
            if (n < NN)
                *(float2*)&g_h1[n * H2 + lane * 2] = acc[t];
        }
    }
}

// ---------------- gather64: agg z2 (g_h1, 64-d), +b2, gelu, normalize -> g_h2/out_h ----------------
__global__ void __launch_bounds__(256) k_gather64(const float* __restrict__ b2,
                                                  float* __restrict__ out_h) {
    int n = (blockIdx.x * 256 + threadIdx.x) >> 5;
    int lane = threadIdx.x & 31;
    if (n >= NN) return;
    const float* src = g_h1;   // 64-d z2
    float2 a = *(const float2*)&src[n * H2 + lane * 2];
    int e0 = g_off[n], e1 = g_off[n + 1];
    int j = e0;
    for (; j + 15 < e1; j += 16) {
        float2 v[16];
#pragma unroll
        for (int u = 0; u < 16; u++) {
            int s = g_csr[j + u];
            v[u] = *(const float2*)&src[s * H2 + lane * 2];
        }
        float sx = 0.f, sy = 0.f;
#pragma unroll
        for (int u = 0; u < 16; u++) { sx += v[u].x; sy += v[u].y; }
        a.x += sx; a.y += sy;
    }
    if (j + 7 < e1) {
        float2 v[8];
#pragma unroll
        for (int u = 0; u < 8; u++) {
            int s = g_csr[j + u];
            v[u] = *(const float2*)&src[s * H2 + lane * 2];
        }
        float sx = 0.f, sy = 0.f;
#pragma unroll
        for (int u = 0; u < 8; u++) { sx += v[u].x; sy += v[u].y; }
        a.x += sx; a.y += sy;
        j += 8;
    }
    for (; j < e1; j++) {
        int s = g_csr[j];
        float2 v = *(const float2*)&src[s * H2 + lane * 2];
        a.x += v.x; a.y += v.y;
    }
    float2 bb = *(const float2*)&b2[lane * 2];
    a.x = gelu_f(a.x + bb.x);
    a.y = gelu_f(a.y + bb.y);
    float ssq = a.x * a.x + a.y * a.y;
#pragma unroll
    for (int off = 16; off; off >>= 1) ssq += __shfl_xor_sync(0xFFFFFFFFu, ssq, off);
    float inv = 1.0f / fmaxf(sqrtf(ssq), 1e-12f);
    a.x *= inv; a.y *= inv;
    *(float2*)&g_h2[n * H2 + lane * 2] = a;
    if (out_h) *(float2*)&out_h[n * H2 + lane * 2] = a;
}

// ---------------- fused Set2Set (4 steps) + final MLP: one block per graph ----------------
__global__ void __launch_bounds__(256) k_s2s(
        const float* __restrict__ Wih0, const float* __restrict__ Whh0,
        const float* __restrict__ bih0, const float* __restrict__ bhh0,
        const float* __restrict__ Wih1, const float* __restrict__ Whh1,
        const float* __restrict__ bih1, const float* __restrict__ bhh1,
        const float* __restrict__ fc1W, const float* __restrict__ fc1b,
        const float* __restrict__ fc2W, const float* __restrict__ fc2b,
        float* __restrict__ z) {
    __shared__ float h0[H2], c0[H2], h1[H2], c1[H2], qs[2 * H2];
    __shared__ float gb[4 * H2], red[8], rbuf[8 * H2];
    __shared__ float smax, ssum;
    int g = blockIdx.x;
    int tid = threadIdx.x, warp = tid >> 5, lane = tid & 31;
    int gs = g_gs[g], ge = g_gs[g + 1];
    if (tid < H2) { h0[tid] = 0.0f; c0[tid] = 0.0f; h1[tid] = 0.0f; c1[tid] = 0.0f; }
    if (tid < 2 * H2) qs[tid] = 0.0f;
    __syncthreads();

    for (int step = 0; step < 4; step++) {
        for (int r = warp; r < 4 * H2; r += 8) {
            const float* wi = &Wih0[r * 2 * H2];
            float p = wi[lane] * qs[lane] + wi[lane + 32] * qs[lane + 32]
                    + wi[lane + 64] * qs[lane + 64] + wi[lane + 96] * qs[lane + 96];
            const float* wh = &Whh0[r * H2];
            p += wh[lane] * h0[lane] + wh[lane + 32] * h0[lane + 32];
#pragma unroll
            for (int off = 16; off; off >>= 1) p += __shfl_xor_sync(0xFFFFFFFFu, p, off);
            if (lane == 0) gb[r] = p + bih0[r] + bhh0[r];
        }
        __syncthreads();
        if (tid < H2) {
            float i = sigmoid_f(gb[tid]);
            float f = sigmoid_f(gb[H2 + tid]);
            float gg = tanhf(gb[2 * H2 + tid]);
            float o = sigmoid_f(gb[3 * H2 + tid]);
            float c = f * c0[tid] + i * gg;
            c0[tid] = c;
            h0[tid] = o * tanhf(c);
        }
        __syncthreads();
        for (int r = warp; r < 4 * H2; r += 8) {
            const float* wi = &Wih1[r * H2];
            float p = wi[lane] * h0[lane] + wi[lane + 32] * h0[lane + 32];
            const float* wh = &Whh1[r * H2];
            p += wh[lane] * h1[lane] + wh[lane + 32] * h1[lane + 32];
#pragma unroll
            for (int off = 16; off; off >>= 1) p += __shfl_xor_sync(0xFFFFFFFFu, p, off);
            if (lane == 0) gb[r] = p + bih1[r] + bhh1[r];
        }
        __syncthreads();
        if (tid < H2) {
            float i = sigmoid_f(gb[tid]);
            float f = sigmoid_f(gb[H2 + tid]);
            float gg = tanhf(gb[2 * H2 + tid]);
            float o = sigmoid_f(gb[3 * H2 + tid]);
            float c = f * c1[tid] + i * gg;
            c1[tid] = c;
            float h = o * tanhf(c);
            h1[tid] = h;
            qs[tid] = h;
        }
        __syncthreads();
        float wmax = -3.4e38f;
        for (int n = gs + warp; n < ge; n += 8) {
            float2 hv = *(const float2*)&g_h2[n * H2 + lane * 2];
            float e = hv.x * qs[lane * 2] + hv.y * qs[lane * 2 + 1];
#pragma unroll
            for (int off = 16; off; off >>= 1) e += __shfl_xor_sync(0xFFFFFFFFu, e, off);
            if (lane == 0) g_e[n] = e;
            wmax = fmaxf(wmax, e);
        }
        if (lane == 0) red[warp] = wmax;
        __syncthreads();
        if (tid == 0) {
            float m = red[0];
            for (int w = 1; w < 8; w++) m = fmaxf(m, red[w]);
            smax = m;
        }
        __syncthreads();
        float m = smax;
        float ps = 0.0f;
        for (int n = gs + tid; n < ge; n += 256) {
            float ex = expf(g_e[n] - m);
            g_e[n] = ex;
            ps += ex;
        }
#pragma unroll
        for (int off = 16; off; off >>= 1) ps += __shfl_xor_sync(0xFFFFFFFFu, ps, off);
        if (lane == 0) red[warp] = ps;
        __syncthreads();
        if (tid == 0) {
            float s = 0.0f;
            for (int w = 0; w < 8; w++) s += red[w];
            ssum = s;
        }
        __syncthreads();
        float inv = 1.0f / (ssum + 1e-16f);
        float rx = 0.0f, ry = 0.0f;
        for (int n = gs + warp; n < ge; n += 8) {
            float a = g_e[n] * inv;
            float2 hv = *(const float2*)&g_h2[n * H2 + lane * 2];
            rx = fmaf(a, hv.x, rx);
            ry = fmaf(a, hv.y, ry);
        }
        rbuf[warp * H2 + lane * 2]     = rx;
        rbuf[warp * H2 + lane * 2 + 1] = ry;
        __syncthreads();
        if (tid < H2) {
            float r = 0.0f;
            for (int w = 0; w < 8; w++) r += rbuf[w * H2 + tid];
            qs[H2 + tid] = r;
        }
        __syncthreads();
    }

    for (int r = warp; r < 32; r += 8) {
        const float* wr = &fc1W[r * 2 * H2];
        float p = wr[lane] * qs[lane] + wr[lane + 32] * qs[lane + 32]
                + wr[lane + 64] * qs[lane + 64] + wr[lane + 96] * qs[lane + 96];
#pragma unroll
        for (int off = 16; off; off >>= 1) p += __shfl_xor_sync(0xFFFFFFFFu, p, off);
        if (lane == 0) gb[r] = gelu_f(p + fc1b[r]);
    }
    __syncthreads();
    if (warp == 0) {
        float v = gb[lane] * fc2W[lane];
#pragma unroll
        for (int off = 16; off; off >>= 1) v += __shfl_xor_sync(0xFFFFFFFFu, v, off);
        if (lane == 0) z[g] = v + fc2b[0];
    }
}

// ---------------- host ----------------
extern "C" void kernel_launch(void* const* d_in, const int* in_sizes, int n_in,
                              void* d_out, int out_size) {
    const float* x     = (const float*)d_in[0];
    const int*   ei    = (const int*)d_in[1];
    const int*   batch = (const int*)d_in[2];
    const float* nfcW  = (const float*)d_in[3];
    const float* nfcb  = (const float*)d_in[4];
    const float* gc1W  = (const float*)d_in[5];
    const float* gc1b  = (const float*)d_in[6];
    const float* gc2W  = (const float*)d_in[7];
    const float* gc2b  = (const float*)d_in[8];
    const float* l0Wih = (const float*)d_in[9];
    const float* l0Whh = (const float*)d_in[10];
    const float* l0bih = (const float*)d_in[11];
    const float* l0bhh = (const float*)d_in[12];
    const float* l1Wih = (const float*)d_in[13];
    const float* l1Whh = (const float*)d_in[14];
    const float* l1bih = (const float*)d_in[15];
    const float* l1bhh = (const float*)d_in[16];
    const float* fc1W  = (const float*)d_in[17];
    const float* fc1b  = (const float*)d_in[18];
    const float* fc2W  = (const float*)d_in[19];
    const float* fc2b  = (const float*)d_in[20];

    float* out = (float*)d_out;
    float* out_h = (out_size >= NG + NN * H2) ? (out + NG) : nullptr;

    int nblk = (NN + TPB - 1) / TPB;                      // 1563
    int gblk = (NN * 32 + 255) / 256;                     // 12500
    size_t sm_nfc   = (size_t)(NF * H1 + TPB * NF) * 4;   // 48 KB
    size_t sm_gemmA = (size_t)(H1 * H1 + TPB * H1) * 4;   // 96 KB
    cudaFuncSetAttribute(k_nfc,   cudaFuncAttributeMaxDynamicSharedMemorySize, (int)sm_nfc);
    cudaFuncSetAttribute(k_gemmA, cudaFuncAttributeMaxDynamicSharedMemorySize, (int)sm_gemmA);

    k_zero<<<128, 256>>>();
    k_nfc<<<nblk, 256, sm_nfc>>>(x, nfcW, nfcb, ei);
    k_scan<<<SCB, 256>>>(batch);
    k_scatter<<<(NE + 255) / 256, 256>>>(ei);
    // conv1 gather (128-d), then fused gemm1+gemm2t, then 64-d conv2 aggregate
    k_gather<<<gblk, 256>>>();
    k_gemmA<<<nblk, 256, sm_gemmA>>>(gc1W, gc1b, gc2W);
    k_gather64<<<gblk, 256>>>(gc2b, out_h);
    k_s2s<<<NG, 256>>>(l0Wih, l0Whh, l0bih, l0bhh,
                       l1Wih, l1Whh, l1bih, l1bhh,
                       fc1W, fc1b, fc2W, fc2b, out);
}

// round 16
// speedup vs baseline: 1.3293x; 1.0119x over previous
#include <cuda_runtime.h>
#include <math.h>

#define NN 100000
#define NE 1600000
#define NG 512
#define NF 64
#define H1 128
#define H2 64
#define SCB 98            // scan blocks: ceil(NN/1024)
#define TPB 64            // nodes per block in dense kernels

// ---------------- device scratch ----------------
__device__ float g_h1[NN * H1];
__device__ float g_s1[NN * H1];
__device__ float g_h2[NN * H2];
__device__ float g_e[NN];
__device__ int   g_cnt[NN];
__device__ int   g_off[NN + 1];
__device__ int   g_cur[NN];
__device__ int   g_csr[NE];
__device__ int   g_gs[NG + 1];
__device__ int   g_sagg[SCB];
__device__ int   g_sflag[SCB];

__device__ __forceinline__ float gelu_f(float x) {
    return 0.5f * x * (1.0f + erff(x * 0.70710678118654752f));
}
__device__ __forceinline__ float sigmoid_f(float x) {
    return 1.0f / (1.0f + expf(-x));
}

// ---------------- init ----------------
__global__ void __launch_bounds__(256) k_zero() {
    int i = blockIdx.x * blockDim.x + threadIdx.x;
    int T = gridDim.x * blockDim.x;
    for (int j = i; j < NN; j += T) { g_cnt[j] = 0; g_cur[j] = 0; }
    if (i < SCB) { g_sflag[i] = 0; g_sagg[i] = 0; }
    if (i == 0) g_off[NN] = NE;
}

// ---------------- edge count (side stream) ----------------
__global__ void __launch_bounds__(256) k_count(const int* __restrict__ ei) {
    int e = blockIdx.x * blockDim.x + threadIdx.x;
    if (e < NE) atomicAdd(&g_cnt[ei[NE + e]], 1);
}

// ---------------- nfc (64 nodes/block), pure ----------------
__global__ void __launch_bounds__(256) k_nfc(const float* __restrict__ x,
                                             const float* __restrict__ W,
                                             const float* __restrict__ b) {
    extern __shared__ float sm[];
    float* wt = sm;                  // [64][128] transposed (32 KB)
    float* xs = sm + NF * H1;        // [64][64]  (16 KB)
    int tid = threadIdx.x;
    for (int i = tid; i < H1 * NF; i += 256) {
        int o = i >> 6, k = i & 63;
        wt[k * H1 + o] = W[i];
    }
    int warp = tid >> 5, lane = tid & 31;
    int nb = blockIdx.x * TPB;
#pragma unroll
    for (int t = 0; t < 8; t++) {
        int row = warp * 8 + t;
        int n = nb + row;
        if (n < NN) {
            float2 xv = *(const float2*)&x[n * NF + lane * 2];
            *(float2*)&xs[row * NF + lane * 2] = xv;
        }
    }
    __syncthreads();
    float4 bias = *(const float4*)&b[lane * 4];
    float4 acc[8];
#pragma unroll
    for (int t = 0; t < 8; t++) acc[t] = bias;
    const float* rp = &xs[warp * 8 * NF];
#pragma unroll 4
    for (int k = 0; k < NF; k++) {
        float4 w = *(const float4*)&wt[k * H1 + lane * 4];
#pragma unroll
        for (int t = 0; t < 8; t++) {
            float v = rp[t * NF + k];
            acc[t].x = fmaf(v, w.x, acc[t].x);
            acc[t].y = fmaf(v, w.y, acc[t].y);
            acc[t].z = fmaf(v, w.z, acc[t].z);
            acc[t].w = fmaf(v, w.w, acc[t].w);
        }
    }
#pragma unroll
    for (int t = 0; t < 8; t++) {
        int n = nb + warp * 8 + t;
        if (n < NN) {
            float4 a = acc[t];
            a.x = gelu_f(a.x); a.y = gelu_f(a.y);
            a.z = gelu_f(a.z); a.w = gelu_f(a.w);
            *(float4*)&g_h1[n * H1 + lane * 4] = a;
        }
    }
}

// ---------------- single-pass scan (decoupled lookback) + gstart fold ----------------
__global__ void __launch_bounds__(256) k_scan(const int* __restrict__ batch) {
    __shared__ int sm[256];
    __shared__ int addsh;
    int tid = threadIdx.x;
    int b = blockIdx.x;
    if (tid == 0) addsh = 0;
    int idx = b * 1024 + tid * 4;
    int v0 = 0, v1 = 0, v2 = 0, v3 = 0;
    if (idx     < NN) v0 = g_cnt[idx];
    if (idx + 1 < NN) v1 = g_cnt[idx + 1];
    if (idx + 2 < NN) v2 = g_cnt[idx + 2];
    if (idx + 3 < NN) v3 = g_cnt[idx + 3];
    int t = v0 + v1 + v2 + v3;
    sm[tid] = t;
    __syncthreads();
    for (int off = 1; off < 256; off <<= 1) {
        int u = (tid >= off) ? sm[tid - off] : 0;
        __syncthreads();
        sm[tid] += u;
        __syncthreads();
    }
    if (tid == 0) {
        g_sagg[b] = sm[255];
        __threadfence();
        atomicExch(&g_sflag[b], 1);
    }
    int excl = sm[tid] - t;
    int myadd = 0;
    for (int i = tid; i < b; i += 256) {
        while (((volatile int*)g_sflag)[i] == 0) { }
        myadd += ((volatile int*)g_sagg)[i];
    }
#pragma unroll
    for (int off = 16; off; off >>= 1) myadd += __shfl_xor_sync(0xFFFFFFFFu, myadd, off);
    if ((tid & 31) == 0 && myadd) atomicAdd(&addsh, myadd);
    __syncthreads();
    int add = addsh;
    if (idx     < NN) g_off[idx]     = excl + add;
    if (idx + 1 < NN) g_off[idx + 1] = excl + add + v0;
    if (idx + 2 < NN) g_off[idx + 2] = excl + add + v0 + v1;
    if (idx + 3 < NN) g_off[idx + 3] = excl + add + v0 + v1 + v2;
#pragma unroll
    for (int i = 0; i < 4; i++) {
        int n = idx + i;
        if (n < NN) {
            int bb = batch[n];
            int bp = (n == 0) ? -1 : batch[n - 1];
            for (int g = bp + 1; g <= bb; g++) g_gs[g] = n;
            if (n == NN - 1)
                for (int g = bb + 1; g <= NG; g++) g_gs[g] = NN;
        }
    }
}

__global__ void __launch_bounds__(256) k_scatter(const int* __restrict__ ei) {
    int e = blockIdx.x * blockDim.x + threadIdx.x;
    if (e < NE) {
        int s = ei[e];
        int d = ei[NE + e];
        int pos = atomicAdd(&g_cur[d], 1);
        g_csr[g_off[d] + pos] = s;
    }
}

// ---------------- gather: warp per node, g_h1 -> g_s1 (128-d) ----------------
__global__ void __launch_bounds__(256) k_gather() {
    int n = (blockIdx.x * 256 + threadIdx.x) >> 5;
    int lane = threadIdx.x & 31;
    if (n >= NN) return;
    const float* src = g_h1;
    float4 a = *(const float4*)&src[n * H1 + lane * 4];
    int e0 = g_off[n], e1 = g_off[n + 1];
    int j = e0;
    for (; j + 7 < e1; j += 8) {
        int s0 = g_csr[j],     s1 = g_csr[j + 1], s2 = g_csr[j + 2], s3 = g_csr[j + 3];
        int s4 = g_csr[j + 4], s5 = g_csr[j + 5], s6 = g_csr[j + 6], s7 = g_csr[j + 7];
        float4 v0 = *(const float4*)&src[s0 * H1 + lane * 4];
        float4 v1 = *(const float4*)&src[s1 * H1 + lane * 4];
        float4 v2 = *(const float4*)&src[s2 * H1 + lane * 4];
        float4 v3 = *(const float4*)&src[s3 * H1 + lane * 4];
        float4 v4 = *(const float4*)&src[s4 * H1 + lane * 4];
        float4 v5 = *(const float4*)&src[s5 * H1 + lane * 4];
        float4 v6 = *(const float4*)&src[s6 * H1 + lane * 4];
        float4 v7 = *(const float4*)&src[s7 * H1 + lane * 4];
        a.x += ((v0.x + v1.x) + (v2.x + v3.x)) + ((v4.x + v5.x) + (v6.x + v7.x));
        a.y += ((v0.y + v1.y) + (v2.y + v3.y)) + ((v4.y + v5.y) + (v6.y + v7.y));
        a.z += ((v0.z + v1.z) + (v2.z + v3.z)) + ((v4.z + v5.z) + (v6.z + v7.z));
        a.w += ((v0.w + v1.w) + (v2.w + v3.w)) + ((v4.w + v5.w) + (v6.w + v7.w));
    }
    if (j + 3 < e1) {
        int s0 = g_csr[j], s1 = g_csr[j + 1], s2 = g_csr[j + 2], s3 = g_csr[j + 3];
        float4 v0 = *(const float4*)&src[s0 * H1 + lane * 4];
        float4 v1 = *(const float4*)&src[s1 * H1 + lane * 4];
        float4 v2 = *(const float4*)&src[s2 * H1 + lane * 4];
        float4 v3 = *(const float4*)&src[s3 * H1 + lane * 4];
        a.x += (v0.x + v1.x) + (v2.x + v3.x);
        a.y += (v0.y + v1.y) + (v2.y + v3.y);
        a.z += (v0.z + v1.z) + (v2.z + v3.z);
        a.w += (v0.w + v1.w) + (v2.w + v3.w);
        j += 4;
    }
    for (; j < e1; j++) {
        int s0 = g_csr[j];
        float4 v0 = *(const float4*)&src[s0 * H1 + lane * 4];
        a.x += v0.x; a.y += v0.y; a.z += v0.z; a.w += v0.w;
    }
    *(float4*)&g_s1[n * H1 + lane * 4] = a;
}

// ---------------- gemmA (fused): y = gelu(agg@W1.T + b1); z2 = y@W2.T -> g_h1(64-d) ----------------
__global__ void __launch_bounds__(256) k_gemmA(const float* __restrict__ W1,
                                               const float* __restrict__ b1,
                                               const float* __restrict__ W2) {
    extern __shared__ float sm[];
    float* wt = sm;                  // phase1: [128][128] W1^T (64 KB); phase2: [128][64] W2^T (32 KB)
    float* as = sm + H1 * H1;        // [64][128] activations (32 KB)
    int tid = threadIdx.x;
    for (int i = tid; i < H1 * H1; i += 256) {
        int o = i >> 7, k = i & 127;
        wt[k * H1 + o] = W1[i];
    }
    int nb = blockIdx.x * TPB;
    for (int i = tid; i < TPB * H1 / 4; i += 256) {
        int row = (i * 4) >> 7;
        int k   = (i * 4) & 127;
        int n = nb + row;
        float4 v = (n < NN) ? *(const float4*)&g_s1[n * H1 + k]
                            : make_float4(0.f, 0.f, 0.f, 0.f);
        *(float4*)&as[row * H1 + k] = v;
    }
    __syncthreads();
    int warp = tid >> 5, lane = tid & 31;
    // ---- phase 1: y = gelu(agg @ W1.T + b1)
    {
        float4 bias = *(const float4*)&b1[lane * 4];
        float4 acc[8];
#pragma unroll
        for (int t = 0; t < 8; t++) acc[t] = bias;
        const float* rp = &as[warp * 8 * H1];
#pragma unroll 4
        for (int k = 0; k < H1; k++) {
            float4 w = *(const float4*)&wt[k * H1 + lane * 4];
#pragma unroll
            for (int t = 0; t < 8; t++) {
                float v = rp[t * H1 + k];
                acc[t].x = fmaf(v, w.x, acc[t].x);
                acc[t].y = fmaf(v, w.y, acc[t].y);
                acc[t].z = fmaf(v, w.z, acc[t].z);
                acc[t].w = fmaf(v, w.w, acc[t].w);
            }
        }
        float* wp = &as[warp * 8 * H1];
#pragma unroll
        for (int t = 0; t < 8; t++) {
            float4 a = acc[t];
            a.x = gelu_f(a.x); a.y = gelu_f(a.y);
            a.z = gelu_f(a.z); a.w = gelu_f(a.w);
            *(float4*)&wp[t * H1 + lane * 4] = a;
        }
    }
    __syncthreads();
    for (int i = tid; i < H2 * H1; i += 256) {
        int o = i >> 7, k = i & 127;
        wt[k * H2 + o] = W2[i];
    }
    __syncthreads();
    // ---- phase 2: z2 = y @ W2.T (64-d out, packed into g_h1)
    {
        float2 acc[8];
#pragma unroll
        for (int t = 0; t < 8; t++) acc[t] = make_float2(0.f, 0.f);
        const float* rp = &as[warp * 8 * H1];
#pragma unroll 4
        for (int k = 0; k < H1; k++) {
            float2 w = *(const float2*)&wt[k * H2 + lane * 2];
#pragma unroll
            for (int t = 0; t < 8; t++) {
                float v = rp[t * H1 + k];
                acc[t].x = fmaf(v, w.x, acc[t].x);
                acc[t].y = fmaf(v, w.y, acc[t].y);
            }
        }
#pragma unroll
        for (int t = 0; t < 8; t++) {
            int n = nb + warp * 8 + t;
            if (n < NN)
                *(float2*)&g_h1[n * H2 + lane * 2] = acc[t];
        }
    }
}

// ---------------- gather64: agg z2 (g_h1, 64-d), +b2, gelu, normalize -> g_h2/out_h ----------------
__global__ void __launch_bounds__(256) k_gather64(const float* __restrict__ b2,
                                                  float* __restrict__ out_h) {
    int n = (blockIdx.x * 256 + threadIdx.x) >> 5;
    int lane = threadIdx.x & 31;
    if (n >= NN) return;
    const float* src = g_h1;   // 64-d z2
    float2 a = *(const float2*)&src[n * H2 + lane * 2];
    int e0 = g_off[n], e1 = g_off[n + 1];
    int j = e0;
    for (; j + 15 < e1; j += 16) {
        float2 v[16];
#pragma unroll
        for (int u = 0; u < 16; u++) {
            int s = g_csr[j + u];
            v[u] = *(const float2*)&src[s * H2 + lane * 2];
        }
        float sx = 0.f, sy = 0.f;
#pragma unroll
        for (int u = 0; u < 16; u++) { sx += v[u].x; sy += v[u].y; }
        a.x += sx; a.y += sy;
    }
    if (j + 7 < e1) {
        float2 v[8];
#pragma unroll
        for (int u = 0; u < 8; u++) {
            int s = g_csr[j + u];
            v[u] = *(const float2*)&src[s * H2 + lane * 2];
        }
        float sx = 0.f, sy = 0.f;
#pragma unroll
        for (int u = 0; u < 8; u++) { sx += v[u].x; sy += v[u].y; }
        a.x += sx; a.y += sy;
        j += 8;
    }
    for (; j < e1; j++) {
        int s = g_csr[j];
        float2 v = *(const float2*)&src[s * H2 + lane * 2];
        a.x += v.x; a.y += v.y;
    }
    float2 bb = *(const float2*)&b2[lane * 2];
    a.x = gelu_f(a.x + bb.x);
    a.y = gelu_f(a.y + bb.y);
    float ssq = a.x * a.x + a.y * a.y;
#pragma unroll
    for (int off = 16; off; off >>= 1) ssq += __shfl_xor_sync(0xFFFFFFFFu, ssq, off);
    float inv = 1.0f / fmaxf(sqrtf(ssq), 1e-12f);
    a.x *= inv; a.y *= inv;
    *(float2*)&g_h2[n * H2 + lane * 2] = a;
    if (out_h) *(float2*)&out_h[n * H2 + lane * 2] = a;
}

// ---------------- fused Set2Set (4 steps) + final MLP: one block per graph ----------------
__global__ void __launch_bounds__(256) k_s2s(
        const float* __restrict__ Wih0, const float* __restrict__ Whh0,
        const float* __restrict__ bih0, const float* __restrict__ bhh0,
        const float* __restrict__ Wih1, const float* __restrict__ Whh1,
        const float* __restrict__ bih1, const float* __restrict__ bhh1,
        const float* __restrict__ fc1W, const float* __restrict__ fc1b,
        const float* __restrict__ fc2W, const float* __restrict__ fc2b,
        float* __restrict__ z) {
    __shared__ float h0[H2], c0[H2], h1[H2], c1[H2], qs[2 * H2];
    __shared__ float gb[4 * H2], red[8], rbuf[8 * H2];
    __shared__ float smax, ssum;
    int g = blockIdx.x;
    int tid = threadIdx.x, warp = tid >> 5, lane = tid & 31;
    int gs = g_gs[g], ge = g_gs[g + 1];
    if (tid < H2) { h0[tid] = 0.0f; c0[tid] = 0.0f; h1[tid] = 0.0f; c1[tid] = 0.0f; }
    if (tid < 2 * H2) qs[tid] = 0.0f;
    __syncthreads();

    for (int step = 0; step < 4; step++) {
        for (int r = warp; r < 4 * H2; r += 8) {
            const float* wi = &Wih0[r * 2 * H2];
            float p = wi[lane] * qs[lane] + wi[lane + 32] * qs[lane + 32]
                    + wi[lane + 64] * qs[lane + 64] + wi[lane + 96] * qs[lane + 96];
            const float* wh = &Whh0[r * H2];
            p += wh[lane] * h0[lane] + wh[lane + 32] * h0[lane + 32];
#pragma unroll
            for (int off = 16; off; off >>= 1) p += __shfl_xor_sync(0xFFFFFFFFu, p, off);
            if (lane == 0) gb[r] = p + bih0[r] + bhh0[r];
        }
        __syncthreads();
        if (tid < H2) {
            float i = sigmoid_f(gb[tid]);
            float f = sigmoid_f(gb[H2 + tid]);
            float gg = tanhf(gb[2 * H2 + tid]);
            float o = sigmoid_f(gb[3 * H2 + tid]);
            float c = f * c0[tid] + i * gg;
            c0[tid] = c;
            h0[tid] = o * tanhf(c);
        }
        __syncthreads();
        for (int r = warp; r < 4 * H2; r += 8) {
            const float* wi = &Wih1[r * H2];
            float p = wi[lane] * h0[lane] + wi[lane + 32] * h0[lane + 32];
            const float* wh = &Whh1[r * H2];
            p += wh[lane] * h1[lane] + wh[lane + 32] * h1[lane + 32];
#pragma unroll
            for (int off = 16; off; off >>= 1) p += __shfl_xor_sync(0xFFFFFFFFu, p, off);
            if (lane == 0) gb[r] = p + bih1[r] + bhh1[r];
        }
        __syncthreads();
        if (tid < H2) {
            float i = sigmoid_f(gb[tid]);
            float f = sigmoid_f(gb[H2 + tid]);
            float gg = tanhf(gb[2 * H2 + tid]);
            float o = sigmoid_f(gb[3 * H2 + tid]);
            float c = f * c1[tid] + i * gg;
            c1[tid] = c;
            float h = o * tanhf(c);
            h1[tid] = h;
            qs[tid] = h;
        }
        __syncthreads();
        float wmax = -3.4e38f;
        for (int n = gs + warp; n < ge; n += 8) {
            float2 hv = *(const float2*)&g_h2[n * H2 + lane * 2];
            float e = hv.x * qs[lane * 2] + hv.y * qs[lane * 2 + 1];
#pragma unroll
            for (int off = 16; off; off >>= 1) e += __shfl_xor_sync(0xFFFFFFFFu, e, off);
            if (lane == 0) g_e[n] = e;
            wmax = fmaxf(wmax, e);
        }
        if (lane == 0) red[warp] = wmax;
        __syncthreads();
        if (tid == 0) {
            float m = red[0];
            for (int w = 1; w < 8; w++) m = fmaxf(m, red[w]);
            smax = m;
        }
        __syncthreads();
        float m = smax;
        float ps = 0.0f;
        for (int n = gs + tid; n < ge; n += 256) {
            float ex = expf(g_e[n] - m);
            g_e[n] = ex;
            ps += ex;
        }
#pragma unroll
        for (int off = 16; off; off >>= 1) ps += __shfl_xor_sync(0xFFFFFFFFu, ps, off);
        if (lane == 0) red[warp] = ps;
        __syncthreads();
        if (tid == 0) {
            float s = 0.0f;
            for (int w = 0; w < 8; w++) s += red[w];
            ssum = s;
        }
        __syncthreads();
        float inv = 1.0f / (ssum + 1e-16f);
        float rx = 0.0f, ry = 0.0f;
        for (int n = gs + warp; n < ge; n += 8) {
            float a = g_e[n] * inv;
            float2 hv = *(const float2*)&g_h2[n * H2 + lane * 2];
            rx = fmaf(a, hv.x, rx);
            ry = fmaf(a, hv.y, ry);
        }
        rbuf[warp * H2 + lane * 2]     = rx;
        rbuf[warp * H2 + lane * 2 + 1] = ry;
        __syncthreads();
        if (tid < H2) {
            float r = 0.0f;
            for (int w = 0; w < 8; w++) r += rbuf[w * H2 + tid];
            qs[H2 + tid] = r;
        }
        __syncthreads();
    }

    for (int r = warp; r < 32; r += 8) {
        const float* wr = &fc1W[r * 2 * H2];
        float p = wr[lane] * qs[lane] + wr[lane + 32] * qs[lane + 32]
                + wr[lane + 64] * qs[lane + 64] + wr[lane + 96] * qs[lane + 96];
#pragma unroll
        for (int off = 16; off; off >>= 1) p += __shfl_xor_sync(0xFFFFFFFFu, p, off);
        if (lane == 0) gb[r] = gelu_f(p + fc1b[r]);
    }
    __syncthreads();
    if (warp == 0) {
        float v = gb[lane] * fc2W[lane];
#pragma unroll
        for (int off = 16; off; off >>= 1) v += __shfl_xor_sync(0xFFFFFFFFu, v, off);
        if (lane == 0) z[g] = v + fc2b[0];
    }
}

// ---------------- host ----------------
extern "C" void kernel_launch(void* const* d_in, const int* in_sizes, int n_in,
                              void* d_out, int out_size) {
    const float* x     = (const float*)d_in[0];
    const int*   ei    = (const int*)d_in[1];
    const int*   batch = (const int*)d_in[2];
    const float* nfcW  = (const float*)d_in[3];
    const float* nfcb  = (const float*)d_in[4];
    const float* gc1W  = (const float*)d_in[5];
    const float* gc1b  = (const float*)d_in[6];
    const float* gc2W  = (const float*)d_in[7];
    const float* gc2b  = (const float*)d_in[8];
    const float* l0Wih = (const float*)d_in[9];
    const float* l0Whh = (const float*)d_in[10];
    const float* l0bih = (const float*)d_in[11];
    const float* l0bhh = (const float*)d_in[12];
    const float* l1Wih = (const float*)d_in[13];
    const float* l1Whh = (const float*)d_in[14];
    const float* l1bih = (const float*)d_in[15];
    const float* l1bhh = (const float*)d_in[16];
    const float* fc1W  = (const float*)d_in[17];
    const float* fc1b  = (const float*)d_in[18];
    const float* fc2W  = (const float*)d_in[19];
    const float* fc2b  = (const float*)d_in[20];

    float* out = (float*)d_out;
    float* out_h = (out_size >= NG + NN * H2) ? (out + NG) : nullptr;

    int nblk = (NN + TPB - 1) / TPB;                      // 1563
    int gblk = (NN * 32 + 255) / 256;                     // 12500
    size_t sm_nfc   = (size_t)(NF * H1 + TPB * NF) * 4;   // 48 KB
    size_t sm_gemmA = (size_t)(H1 * H1 + TPB * H1) * 4;   // 96 KB

    // one-time setup (first call is the non-captured correctness run)
    static cudaStream_t side = nullptr;
    static cudaEvent_t evFork = nullptr, evJoin = nullptr;
    if (!side) {
        cudaStreamCreateWithFlags(&side, cudaStreamNonBlocking);
        cudaEventCreateWithFlags(&evFork, cudaEventDisableTiming);
        cudaEventCreateWithFlags(&evJoin, cudaEventDisableTiming);
        cudaFuncSetAttribute(k_nfc,   cudaFuncAttributeMaxDynamicSharedMemorySize, (int)sm_nfc);
        cudaFuncSetAttribute(k_gemmA, cudaFuncAttributeMaxDynamicSharedMemorySize, (int)sm_gemmA);
    }

    k_zero<<<128, 256>>>();
    // fork: CSR build chain on side stream, nfc on main stream (independent)
    cudaEventRecord(evFork, 0);
    cudaStreamWaitEvent(side, evFork, 0);
    k_count<<<(NE + 255) / 256, 256, 0, side>>>(ei);
    k_scan<<<SCB, 256, 0, side>>>(batch);
    k_scatter<<<(NE + 255) / 256, 256, 0, side>>>(ei);
    cudaEventRecord(evJoin, side);
    k_nfc<<<nblk, 256, sm_nfc>>>(x, nfcW, nfcb);
    cudaStreamWaitEvent(0, evJoin, 0);
    // join: both h1 and CSR ready
    k_gather<<<gblk, 256>>>();
    k_gemmA<<<nblk, 256, sm_gemmA>>>(gc1W, gc1b, gc2W);
    k_gather64<<<gblk, 256>>>(gc2b, out_h);
    k_s2s<<<NG, 256>>>(l0Wih, l0Whh, l0bih, l0bhh,
                       l1Wih, l1Whh, l1bih, l1bhh,
                       fc1W, fc1b, fc2W, fc2b, out);
}